// round 1
// baseline (speedup 1.0000x reference)
#include <cuda_runtime.h>
#include <math.h>

#define T_LEN 1024
#define B_SZ  64
#define DH    256
#define NL    8
#define OUTL  24
#define M_TOT (B_SZ * T_LEN)   // 65536 rows

// ---------------- scratch (device globals; no cudaMalloc allowed) ----------
__device__ float g_h[M_TOT * DH];        // activations (b, t, c)
__device__ float g_gated[M_TOT * DH];    // gated conv output
__device__ float g_skip[M_TOT * DH];     // skip accumulator
__device__ float g_Wc[NL * 3 * DH * 512]; // conv weights transposed: [i][k][ic][oc512]
__device__ float g_Ws[NL * DH * 512];     // skip weights transposed: [i][ic][oc512]
__device__ float g_loss;

// ---------------- weight pre-transpose + loss zero --------------------------
__global__ void prep_weights(const float* __restrict__ conv_w,
                             const float* __restrict__ skip_w) {
    int idx = blockIdx.x * blockDim.x + threadIdx.x;
    if (idx == 0) g_loss = 0.0f;
    const int totC = NL * 3 * DH * 512;
    if (idx < totC) {
        int oc = idx % 512;
        int tmp = idx / 512;
        int ic = tmp % DH;
        tmp /= DH;
        int k = tmp % 3;
        int i = tmp / 3;
        // conv_dil_w: (NL, 512, 256, 3)
        g_Wc[idx] = conv_w[((size_t)(i * 512 + oc) * DH + ic) * 3 + k];
    }
    const int totS = NL * DH * 512;
    if (idx < totS) {
        int oc = idx % 512;
        int tmp = idx / 512;
        int ic = tmp % DH;
        int i = tmp / DH;
        // skip_w: (NL, 512, 256)
        g_Ws[idx] = skip_w[(size_t)(i * 512 + oc) * DH + ic];
    }
}

// ---------------- up projection: h = [X_lag, X_cov] @ up_w + up_b ----------
__global__ __launch_bounds__(256) void up_kernel(
    const float* __restrict__ X_lag, const float* __restrict__ X_cov,
    const float* __restrict__ up_w, const float* __restrict__ up_b) {
    int r = blockIdx.x;          // r = b*T + t
    int b = r / T_LEN;
    int t = r % T_LEN;
    __shared__ float x[16];
    int c = threadIdx.x;
    if (c < 8)  x[c] = X_lag[((size_t)t * B_SZ + b) * 8 + c];
    else if (c < 16) x[c] = X_cov[((size_t)t * B_SZ + b) * 8 + (c - 8)];
    __syncthreads();
    float acc = up_b[c];
#pragma unroll
    for (int j = 0; j < 16; j++) acc += x[j] * up_w[j * DH + c];
    g_h[(size_t)r * DH + c] = acc;
    g_skip[(size_t)r * DH + c] = 0.0f;
}

// ---------------- per-layer gated dilated conv as 3-tap GEMM ----------------
// grid: (4, 512); CTA computes 128 rows x 64 gated channels
// (= 128 fg accumulator cols: 64 f + 64 g)
#define BM 128
#define BK 16

__global__ __launch_bounds__(256) void conv_gated(int layer, int dil,
                                                  const float* __restrict__ conv_b) {
    __shared__ float As[BK][BM + 4];
    __shared__ float Bs[BK][128];
    const int tid = threadIdx.x;
    const int tx = tid & 15;
    const int ty = tid >> 4;
    const int m0 = blockIdx.y * BM;
    const int g0 = blockIdx.x * 64;     // gated channel base
    const int t0 = m0 % T_LEN;          // tile stays within one batch element
    const float* Wbase = g_Wc + (size_t)layer * 3 * DH * 512;

    float acc[8][8];
#pragma unroll
    for (int a = 0; a < 8; a++)
#pragma unroll
        for (int b = 0; b < 8; b++) acc[a][b] = 0.0f;

    for (int k = 0; k < 3; k++) {
        const int off = (2 - k) * dil;
        const float* Wk = Wbase + (size_t)k * DH * 512;
        for (int kk = 0; kk < DH; kk += BK) {
            // load A tile (128 rows x 16 cols), shifted by off, zero-guarded
#pragma unroll
            for (int s = 0; s < 2; s++) {
                int slot = tid + s * 256;     // 512 float4 slots
                int row = slot >> 2;          // 0..127
                int c4 = slot & 3;            // 0..3
                float4 v = make_float4(0.f, 0.f, 0.f, 0.f);
                if (t0 + row >= off) {
                    const float* p = g_h + (size_t)(m0 + row - off) * DH + kk + c4 * 4;
                    v = *(const float4*)p;
                }
                As[c4 * 4 + 0][row] = v.x;
                As[c4 * 4 + 1][row] = v.y;
                As[c4 * 4 + 2][row] = v.z;
                As[c4 * 4 + 3][row] = v.w;
            }
            // load B tile: 16 ic-rows x (64 f cols @ g0, 64 g cols @ 256+g0)
#pragma unroll
            for (int s = 0; s < 2; s++) {
                int slot = tid + s * 256;     // 512 float4 slots
                int row = slot >> 5;          // 0..15
                int cc = slot & 31;           // 0..31 float4 cols
                int half = cc >> 4;           // 0 = f, 1 = g
                int c4 = cc & 15;
                int oc = (half ? 256 + g0 : g0) + c4 * 4;
                float4 v = *(const float4*)(Wk + (size_t)(kk + row) * 512 + oc);
                *(float4*)&Bs[row][half * 64 + c4 * 4] = v;
            }
            __syncthreads();
#pragma unroll
            for (int p = 0; p < BK; p++) {
                float a[8], bf[8];
                *(float4*)&a[0] = *(const float4*)&As[p][ty * 8];
                *(float4*)&a[4] = *(const float4*)&As[p][ty * 8 + 4];
                *(float4*)&bf[0] = *(const float4*)&Bs[p][tx * 4];        // f weights
                *(float4*)&bf[4] = *(const float4*)&Bs[p][64 + tx * 4];   // g weights
#pragma unroll
                for (int jm = 0; jm < 8; jm++)
#pragma unroll
                    for (int jn = 0; jn < 8; jn++)
                        acc[jm][jn] += a[jm] * bf[jn];
            }
            __syncthreads();
        }
    }
    // epilogue: gated = tanh(f) * sigmoid(g)
    const float* cb = conv_b + layer * 512;
#pragma unroll
    for (int jm = 0; jm < 8; jm++) {
        size_t r = (size_t)(m0 + ty * 8 + jm);
#pragma unroll
        for (int jn = 0; jn < 4; jn++) {
            int ch = g0 + tx * 4 + jn;
            float f = acc[jm][jn] + cb[ch];
            float g = acc[jm][jn + 4] + cb[256 + ch];
            float gated = tanhf(f) * (1.0f / (1.0f + expf(-g)));
            g_gated[r * DH + ch] = gated;
        }
    }
}

// ---------------- per-layer skip projection GEMM -----------------------------
// grid: (4, 512); CTA computes 128 rows x 128 output channels of hs(512)
__global__ __launch_bounds__(256) void skip_gemm(int layer,
                                                 const float* __restrict__ skip_b) {
    __shared__ float As[BK][BM + 4];
    __shared__ float Bs[BK][128];
    const int tid = threadIdx.x;
    const int tx = tid & 15;
    const int ty = tid >> 4;
    const int m0 = blockIdx.y * BM;
    const int n0 = blockIdx.x * 128;
    const float* Wb = g_Ws + (size_t)layer * DH * 512;

    float acc[8][8];
#pragma unroll
    for (int a = 0; a < 8; a++)
#pragma unroll
        for (int b = 0; b < 8; b++) acc[a][b] = 0.0f;

    for (int kk = 0; kk < DH; kk += BK) {
#pragma unroll
        for (int s = 0; s < 2; s++) {
            int slot = tid + s * 256;
            int row = slot >> 2;
            int c4 = slot & 3;
            float4 v = *(const float4*)(g_gated + (size_t)(m0 + row) * DH + kk + c4 * 4);
            As[c4 * 4 + 0][row] = v.x;
            As[c4 * 4 + 1][row] = v.y;
            As[c4 * 4 + 2][row] = v.z;
            As[c4 * 4 + 3][row] = v.w;
        }
#pragma unroll
        for (int s = 0; s < 2; s++) {
            int slot = tid + s * 256;
            int row = slot >> 5;
            int cc = slot & 31;
            float4 v = *(const float4*)(Wb + (size_t)(kk + row) * 512 + n0 + cc * 4);
            *(float4*)&Bs[row][cc * 4] = v;
        }
        __syncthreads();
#pragma unroll
        for (int p = 0; p < BK; p++) {
            float a[8], bf[8];
            *(float4*)&a[0] = *(const float4*)&As[p][ty * 8];
            *(float4*)&a[4] = *(const float4*)&As[p][ty * 8 + 4];
            *(float4*)&bf[0] = *(const float4*)&Bs[p][tx * 8];
            *(float4*)&bf[4] = *(const float4*)&Bs[p][tx * 8 + 4];
#pragma unroll
            for (int jm = 0; jm < 8; jm++)
#pragma unroll
                for (int jn = 0; jn < 8; jn++)
                    acc[jm][jn] += a[jm] * bf[jn];
        }
        __syncthreads();
    }
    const float* sb = skip_b + layer * 512;
#pragma unroll
    for (int jm = 0; jm < 8; jm++) {
        size_t r = (size_t)(m0 + ty * 8 + jm);
#pragma unroll
        for (int jn = 0; jn < 8; jn++) {
            int oc = n0 + tx * 8 + jn;
            float v = acc[jm][jn] + sb[oc];
            if (oc < 256) g_h[r * DH + oc] += v;
            else          g_skip[r * DH + (oc - 256)] += v;
        }
    }
}

// ---------------- FC head + Gaussian NLL over last 24 steps -----------------
__global__ __launch_bounds__(256) void final_k(
    const float* __restrict__ y,
    const float* __restrict__ fc_w, const float* __restrict__ fc_b,
    const float* __restrict__ loc_w, const float* __restrict__ loc_b,
    const float* __restrict__ scale_w, const float* __restrict__ scale_b,
    float* __restrict__ out) {
    int row = blockIdx.x;           // row = tt*B + b  (loc layout (24, B, 1))
    int tt = row >> 6;
    int b = row & 63;
    int t = T_LEN - OUTL + tt;
    size_t r = (size_t)b * T_LEN + t;
    __shared__ float srow[DH];
    __shared__ float red[256];
    int c = threadIdx.x;
    srow[c] = g_skip[r * DH + c];
    __syncthreads();
    float acc = fc_b[c];
#pragma unroll 8
    for (int k = 0; k < DH; k++) acc += srow[k] * fc_w[k * DH + c];
    float ff = fmaxf(acc, 0.0f);

    // loc reduction
    red[c] = ff * loc_w[c];
    __syncthreads();
    for (int s = 128; s > 0; s >>= 1) {
        if (c < s) red[c] += red[c + s];
        __syncthreads();
    }
    float loc = red[0] + loc_b[0];
    __syncthreads();

    // scale reduction
    red[c] = ff * scale_w[c];
    __syncthreads();
    for (int s = 128; s > 0; s >>= 1) {
        if (c < s) red[c] += red[c + s];
        __syncthreads();
    }
    if (c == 0) {
        float sraw = red[0] + scale_b[0];
        float sp = (sraw > 20.0f) ? sraw : log1pf(expf(sraw));
        float scale = sp + 1e-6f;
        float yt = y[(size_t)t * B_SZ + b];
        float z = (yt - loc) / scale;
        float lp = -0.5f * z * z - logf(scale) - 0.91893853320467274f; // 0.5*log(2*pi)
        out[2 + row] = loc;
        out[2 + OUTL * B_SZ + row] = scale;
        atomicAdd(&g_loss, lp);
    }
}

__global__ void finish_k(float* __restrict__ out) {
    float L = -g_loss / (float)(OUTL * B_SZ);
    out[0] = L;
    out[1] = L;
}

// ---------------- launch --------------------------------------------------
extern "C" void kernel_launch(void* const* d_in, const int* in_sizes, int n_in,
                              void* d_out, int out_size) {
    const float* X_cov   = (const float*)d_in[1];
    const float* X_lag   = (const float*)d_in[2];
    const float* y       = (const float*)d_in[3];
    const float* up_w    = (const float*)d_in[5];
    const float* up_b    = (const float*)d_in[6];
    const float* conv_w  = (const float*)d_in[7];
    const float* conv_b  = (const float*)d_in[8];
    const float* skip_w  = (const float*)d_in[9];
    const float* skip_b  = (const float*)d_in[10];
    const float* fc_w    = (const float*)d_in[11];
    const float* fc_b    = (const float*)d_in[12];
    const float* loc_w   = (const float*)d_in[13];
    const float* loc_b   = (const float*)d_in[14];
    const float* scale_w = (const float*)d_in[15];
    const float* scale_b = (const float*)d_in[16];
    float* out = (float*)d_out;

    const int prepTot = NL * 3 * DH * 512;
    prep_weights<<<(prepTot + 255) / 256, 256>>>(conv_w, skip_w);
    up_kernel<<<M_TOT, 256>>>(X_lag, X_cov, up_w, up_b);
    for (int i = 0; i < NL; i++) {
        conv_gated<<<dim3(4, 512), 256>>>(i, 1 << i, conv_b);
        skip_gemm<<<dim3(4, 512), 256>>>(i, skip_b);
    }
    final_k<<<OUTL * B_SZ, 256>>>(y, fc_w, fc_b, loc_w, loc_b, scale_w, scale_b, out);
    finish_k<<<1, 1>>>(out);
}

// round 3
// speedup vs baseline: 1.9022x; 1.9022x over previous
#include <cuda_runtime.h>
#include <cuda_bf16.h>
#include <cstdint>
#include <math.h>

#define T_LEN 1024
#define B_SZ  64
#define DH    256
#define NL    8
#define OUTL  24
#define M_TOT (B_SZ * T_LEN)

// ---------------- device scratch -------------------------------------------
__device__ __align__(128) float          g_h   [M_TOT * DH];   // fp32 master h
__device__ __align__(128) float          g_skip[M_TOT * DH];   // fp32 skip accum
__device__ __align__(128) __nv_bfloat16  g_hhi [M_TOT * DH];
__device__ __align__(128) __nv_bfloat16  g_hlo [M_TOT * DH];
__device__ __align__(128) __nv_bfloat16  g_ghi [M_TOT * DH];   // gated hi
__device__ __align__(128) __nv_bfloat16  g_glo [M_TOT * DH];   // gated lo
// conv weights: [layer][tap][np=512][ic=256], np = 2*c + s (s=0: f ch c, s=1: g ch c)
__device__ __align__(128) __nv_bfloat16  g_Wc_hi[NL * 3 * 512 * DH];
__device__ __align__(128) __nv_bfloat16  g_Wc_lo[NL * 3 * 512 * DH];
// skip weights: [layer][oc=512][ic=256]
__device__ __align__(128) __nv_bfloat16  g_Ws_hi[NL * 512 * DH];
__device__ __align__(128) __nv_bfloat16  g_Ws_lo[NL * 512 * DH];
__device__ float g_loss;

// ---------------- PTX helpers ------------------------------------------------
__device__ __forceinline__ uint32_t cvta_s(const void* p) {
    uint32_t a;
    asm("{ .reg .u64 t; cvta.to.shared.u64 t, %1; cvt.u32.u64 %0, t; }" : "=r"(a) : "l"(p));
    return a;
}
__device__ __forceinline__ void ldsm4(uint32_t (&r)[4], uint32_t addr) {
    asm volatile("ldmatrix.sync.aligned.m8n8.x4.shared.b16 {%0,%1,%2,%3}, [%4];"
                 : "=r"(r[0]), "=r"(r[1]), "=r"(r[2]), "=r"(r[3]) : "r"(addr));
}
__device__ __forceinline__ void mma16816(float (&c)[4], const uint32_t (&a)[4],
                                         uint32_t b0, uint32_t b1) {
    asm volatile(
        "mma.sync.aligned.m16n8k16.row.col.f32.bf16.bf16.f32 "
        "{%0,%1,%2,%3}, {%4,%5,%6,%7}, {%8,%9}, {%0,%1,%2,%3};"
        : "+f"(c[0]), "+f"(c[1]), "+f"(c[2]), "+f"(c[3])
        : "r"(a[0]), "r"(a[1]), "r"(a[2]), "r"(a[3]), "r"(b0), "r"(b1));
}

// smem: 4 planes (A_hi, A_lo, B_hi, B_lo), each 128 rows x 32 bf16, stride 40 elems (80B)
#define PL_SZ 10240
#define ROW_B 80

// ---------------- weight pack + init -----------------------------------------
__global__ void prep_weights(const float* __restrict__ conv_w,
                             const float* __restrict__ skip_w) {
    int idx = blockIdx.x * blockDim.x + threadIdx.x;
    if (idx == 0) g_loss = 0.0f;
    const int totC = NL * 3 * 512 * DH;
    if (idx < totC) {
        int ic = idx & 255;
        int np = (idx >> 8) & 511;
        int tap = (idx >> 17) % 3;
        int layer = idx / (3 * 512 * 256);
        int c = np >> 1, s = np & 1;
        int oc = c + s * 256;
        float v = conv_w[((size_t)(layer * 512 + oc) * DH + ic) * 3 + tap];
        __nv_bfloat16 hi = __float2bfloat16(v);
        g_Wc_hi[idx] = hi;
        g_Wc_lo[idx] = __float2bfloat16(v - __bfloat162float(hi));
    }
    const int totS = NL * 512 * DH;
    if (idx < totS) {
        float v = skip_w[idx];
        __nv_bfloat16 hi = __float2bfloat16(v);
        g_Ws_hi[idx] = hi;
        g_Ws_lo[idx] = __float2bfloat16(v - __bfloat162float(hi));
    }
}

// ---------------- up projection -----------------------------------------------
__global__ __launch_bounds__(256) void up_kernel(
    const float* __restrict__ X_lag, const float* __restrict__ X_cov,
    const float* __restrict__ up_w, const float* __restrict__ up_b) {
    int r = blockIdx.x;
    int b = r / T_LEN;
    int t = r % T_LEN;
    __shared__ float x[16];
    int c = threadIdx.x;
    if (c < 8)       x[c] = X_lag[((size_t)t * B_SZ + b) * 8 + c];
    else if (c < 16) x[c] = X_cov[((size_t)t * B_SZ + b) * 8 + (c - 8)];
    __syncthreads();
    float acc = up_b[c];
#pragma unroll
    for (int j = 0; j < 16; j++) acc += x[j] * up_w[j * DH + c];
    size_t o = (size_t)r * DH + c;
    g_h[o] = acc;
    __nv_bfloat16 hi = __float2bfloat16(acc);
    g_hhi[o] = hi;
    g_hlo[o] = __float2bfloat16(acc - __bfloat162float(hi));
}

// ---------------- conv gated HMMA kernel ---------------------------------------
// grid (4, 512): x = N-tile (128 packed = 64 channels x (f,g)), y = M-tile (128)
__global__ __launch_bounds__(256, 2) void conv_mma(int layer, int dil,
                                                   const float* __restrict__ conv_b) {
    __shared__ __align__(16) unsigned char sm[4 * PL_SZ];
    const int tid = threadIdx.x, wid = tid >> 5, lid = tid & 31;
    const int wm = wid & 1, wn = wid >> 1;
    const int n0 = blockIdx.x * 128, m0 = blockIdx.y * 128;
    const int t0 = m0 & (T_LEN - 1);
    const uint32_t smb = cvta_s(sm);
    const int lrow = lid & 15, lcolb = (lid >> 4) * 16;

    float acc[4][4][4];
#pragma unroll
    for (int a = 0; a < 4; a++)
#pragma unroll
        for (int b = 0; b < 4; b++)
#pragma unroll
            for (int d = 0; d < 4; d++) acc[a][b][d] = 0.0f;

    for (int tap = 0; tap < 3; tap++) {
        const int off = (2 - tap) * dil;
        const __nv_bfloat16* Ah = g_hhi + ((long)m0 - off) * DH;
        const __nv_bfloat16* Al = g_hlo + ((long)m0 - off) * DH;
        const __nv_bfloat16* Bh = g_Wc_hi + ((size_t)(layer * 3 + tap) * 512 + n0) * DH;
        const __nv_bfloat16* Bl = g_Wc_lo + ((size_t)(layer * 3 + tap) * 512 + n0) * DH;
        for (int kc = 0; kc < 8; kc++) {
            const int kk = kc * 32;
            __syncthreads();
#pragma unroll
            for (int i = 0; i < 8; i++) {
                int plane = i >> 1;
                int r = ((i & 1) << 6) + (tid >> 2);
                int c4 = tid & 3;
                const __nv_bfloat16* src = (plane == 0) ? Ah : (plane == 1) ? Al
                                         : (plane == 2) ? Bh : Bl;
                uint4 v = make_uint4(0u, 0u, 0u, 0u);
                if (plane >= 2 || (t0 + r) >= off)
                    v = *(const uint4*)(src + (long)r * DH + kk + c4 * 8);
                *(uint4*)(sm + plane * PL_SZ + r * ROW_B + c4 * 16) = v;
            }
            __syncthreads();
#pragma unroll
            for (int ks = 0; ks < 2; ks++) {
                uint32_t a[4][4], bH[2][4], bL[2][4];
#pragma unroll
                for (int q = 0; q < 2; q++) {
                    uint32_t bd = smb + 2 * PL_SZ + (wn * 32 + q * 16 + lrow) * ROW_B
                                + ks * 32 + lcolb;
                    ldsm4(bH[q], bd);
                    ldsm4(bL[q], bd + PL_SZ);
                }
#pragma unroll
                for (int mt = 0; mt < 4; mt++)
                    ldsm4(a[mt], smb + (wm * 64 + mt * 16 + lrow) * ROW_B + ks * 32 + lcolb);
#pragma unroll
                for (int mt = 0; mt < 4; mt++)
#pragma unroll
                    for (int nt = 0; nt < 4; nt++) {
                        int q = nt >> 1, h = nt & 1;
                        mma16816(acc[mt][nt], a[mt], bH[q][h], bH[q][h + 2]);
                        mma16816(acc[mt][nt], a[mt], bL[q][h], bL[q][h + 2]);
                    }
#pragma unroll
                for (int mt = 0; mt < 4; mt++)
                    ldsm4(a[mt], smb + PL_SZ + (wm * 64 + mt * 16 + lrow) * ROW_B
                                + ks * 32 + lcolb);
#pragma unroll
                for (int mt = 0; mt < 4; mt++)
#pragma unroll
                    for (int nt = 0; nt < 4; nt++) {
                        int q = nt >> 1, h = nt & 1;
                        mma16816(acc[mt][nt], a[mt], bH[q][h], bH[q][h + 2]);
                    }
            }
        }
    }
    // epilogue: lane cols are (f,g) of one channel
    const float* cbf = conv_b + layer * 512;
    const int lm = lid >> 2, ln = lid & 3;
#pragma unroll
    for (int mt = 0; mt < 4; mt++) {
        int row0 = m0 + wm * 64 + mt * 16 + lm;
#pragma unroll
        for (int nt = 0; nt < 4; nt++) {
            int ch = ((n0 + wn * 32 + nt * 8) >> 1) + ln;
            float fb = __ldg(cbf + ch), gb = __ldg(cbf + 256 + ch);
#pragma unroll
            for (int u = 0; u < 2; u++) {
                int row = row0 + u * 8;
                float f = acc[mt][nt][2 * u] + fb;
                float g = acc[mt][nt][2 * u + 1] + gb;
                float e2f = __expf(2.0f * f);
                float th = (e2f - 1.0f) / (e2f + 1.0f);
                float val = th / (1.0f + __expf(-g));
                __nv_bfloat16 hi = __float2bfloat16(val);
                g_ghi[(size_t)row * DH + ch] = hi;
                g_glo[(size_t)row * DH + ch] = __float2bfloat16(val - __bfloat162float(hi));
            }
        }
    }
}

// ---------------- skip projection HMMA kernel -----------------------------------
// grid (4, 512): x = N-tile of hs(512), y = M-tile
__global__ __launch_bounds__(256, 2) void skip_mma(int layer,
                                                   const float* __restrict__ skip_b) {
    __shared__ __align__(16) unsigned char sm[4 * PL_SZ];
    const int tid = threadIdx.x, wid = tid >> 5, lid = tid & 31;
    const int wm = wid & 1, wn = wid >> 1;
    const int n0 = blockIdx.x * 128, m0 = blockIdx.y * 128;
    const uint32_t smb = cvta_s(sm);
    const int lrow = lid & 15, lcolb = (lid >> 4) * 16;

    float acc[4][4][4];
#pragma unroll
    for (int a = 0; a < 4; a++)
#pragma unroll
        for (int b = 0; b < 4; b++)
#pragma unroll
            for (int d = 0; d < 4; d++) acc[a][b][d] = 0.0f;

    const __nv_bfloat16* Ah = g_ghi + (size_t)m0 * DH;
    const __nv_bfloat16* Al = g_glo + (size_t)m0 * DH;
    const __nv_bfloat16* Bh = g_Ws_hi + ((size_t)layer * 512 + n0) * DH;
    const __nv_bfloat16* Bl = g_Ws_lo + ((size_t)layer * 512 + n0) * DH;

    for (int kc = 0; kc < 8; kc++) {
        const int kk = kc * 32;
        __syncthreads();
#pragma unroll
        for (int i = 0; i < 8; i++) {
            int plane = i >> 1;
            int r = ((i & 1) << 6) + (tid >> 2);
            int c4 = tid & 3;
            const __nv_bfloat16* src = (plane == 0) ? Ah : (plane == 1) ? Al
                                     : (plane == 2) ? Bh : Bl;
            uint4 v = *(const uint4*)(src + (long)r * DH + kk + c4 * 8);
            *(uint4*)(sm + plane * PL_SZ + r * ROW_B + c4 * 16) = v;
        }
        __syncthreads();
#pragma unroll
        for (int ks = 0; ks < 2; ks++) {
            uint32_t a[4][4], bH[2][4], bL[2][4];
#pragma unroll
            for (int q = 0; q < 2; q++) {
                uint32_t bd = smb + 2 * PL_SZ + (wn * 32 + q * 16 + lrow) * ROW_B
                            + ks * 32 + lcolb;
                ldsm4(bH[q], bd);
                ldsm4(bL[q], bd + PL_SZ);
            }
#pragma unroll
            for (int mt = 0; mt < 4; mt++)
                ldsm4(a[mt], smb + (wm * 64 + mt * 16 + lrow) * ROW_B + ks * 32 + lcolb);
#pragma unroll
            for (int mt = 0; mt < 4; mt++)
#pragma unroll
                for (int nt = 0; nt < 4; nt++) {
                    int q = nt >> 1, h = nt & 1;
                    mma16816(acc[mt][nt], a[mt], bH[q][h], bH[q][h + 2]);
                    mma16816(acc[mt][nt], a[mt], bL[q][h], bL[q][h + 2]);
                }
#pragma unroll
            for (int mt = 0; mt < 4; mt++)
                ldsm4(a[mt], smb + PL_SZ + (wm * 64 + mt * 16 + lrow) * ROW_B + ks * 32 + lcolb);
#pragma unroll
            for (int mt = 0; mt < 4; mt++)
#pragma unroll
                for (int nt = 0; nt < 4; nt++) {
                    int q = nt >> 1, h = nt & 1;
                    mma16816(acc[mt][nt], a[mt], bH[q][h], bH[q][h + 2]);
                }
        }
    }
    // epilogue
    const float* sb = skip_b + layer * 512;
    const int lm = lid >> 2, ln = lid & 3;
    const bool is_h = (n0 < 256);
#pragma unroll
    for (int mt = 0; mt < 4; mt++) {
        int row0 = m0 + wm * 64 + mt * 16 + lm;
#pragma unroll
        for (int nt = 0; nt < 4; nt++) {
            int oc = n0 + wn * 32 + nt * 8 + 2 * ln;
            float b0 = __ldg(sb + oc), b1 = __ldg(sb + oc + 1);
#pragma unroll
            for (int u = 0; u < 2; u++) {
                int row = row0 + u * 8;
                float v0 = acc[mt][nt][2 * u] + b0;
                float v1 = acc[mt][nt][2 * u + 1] + b1;
                if (is_h) {
                    float2* hp = (float2*)(g_h + (size_t)row * DH + oc);
                    float2 cur = *hp;
                    float nh0 = cur.x + v0, nh1 = cur.y + v1;
                    *hp = make_float2(nh0, nh1);
                    __nv_bfloat16 a0 = __float2bfloat16(nh0);
                    __nv_bfloat16 a1 = __float2bfloat16(nh1);
                    *(__nv_bfloat162*)(g_hhi + (size_t)row * DH + oc) = __nv_bfloat162(a0, a1);
                    *(__nv_bfloat162*)(g_hlo + (size_t)row * DH + oc) = __nv_bfloat162(
                        __float2bfloat16(nh0 - __bfloat162float(a0)),
                        __float2bfloat16(nh1 - __bfloat162float(a1)));
                } else {
                    float2* sp = (float2*)(g_skip + (size_t)row * DH + (oc - 256));
                    float2 prev = (layer == 0) ? make_float2(0.f, 0.f) : *sp;
                    *sp = make_float2(prev.x + v0, prev.y + v1);
                }
            }
        }
    }
}

// ---------------- FC head + Gaussian NLL ------------------------------------
__global__ __launch_bounds__(256) void final_k(
    const float* __restrict__ y,
    const float* __restrict__ fc_w, const float* __restrict__ fc_b,
    const float* __restrict__ loc_w, const float* __restrict__ loc_b,
    const float* __restrict__ scale_w, const float* __restrict__ scale_b,
    float* __restrict__ out) {
    int row = blockIdx.x;
    int tt = row >> 6;
    int b = row & 63;
    int t = T_LEN - OUTL + tt;
    size_t r = (size_t)b * T_LEN + t;
    __shared__ float srow[DH];
    __shared__ float red[256];
    int c = threadIdx.x;
    srow[c] = g_skip[r * DH + c];
    __syncthreads();
    float acc = fc_b[c];
#pragma unroll 8
    for (int k = 0; k < DH; k++) acc += srow[k] * fc_w[k * DH + c];
    float ff = fmaxf(acc, 0.0f);

    red[c] = ff * loc_w[c];
    __syncthreads();
    for (int s = 128; s > 0; s >>= 1) {
        if (c < s) red[c] += red[c + s];
        __syncthreads();
    }
    float loc = red[0] + loc_b[0];
    __syncthreads();

    red[c] = ff * scale_w[c];
    __syncthreads();
    for (int s = 128; s > 0; s >>= 1) {
        if (c < s) red[c] += red[c + s];
        __syncthreads();
    }
    if (c == 0) {
        float sraw = red[0] + scale_b[0];
        float sp = (sraw > 20.0f) ? sraw : log1pf(expf(sraw));
        float scale = sp + 1e-6f;
        float yt = y[(size_t)t * B_SZ + b];
        float z = (yt - loc) / scale;
        float lp = -0.5f * z * z - logf(scale) - 0.91893853320467274f;
        out[2 + row] = loc;
        out[2 + OUTL * B_SZ + row] = scale;
        atomicAdd(&g_loss, lp);
    }
}

__global__ void finish_k(float* __restrict__ out) {
    float L = -g_loss / (float)(OUTL * B_SZ);
    out[0] = L;
    out[1] = L;
}

// ---------------- launch -----------------------------------------------------
extern "C" void kernel_launch(void* const* d_in, const int* in_sizes, int n_in,
                              void* d_out, int out_size) {
    const float* X_cov   = (const float*)d_in[1];
    const float* X_lag   = (const float*)d_in[2];
    const float* y       = (const float*)d_in[3];
    const float* up_w    = (const float*)d_in[5];
    const float* up_b    = (const float*)d_in[6];
    const float* conv_w  = (const float*)d_in[7];
    const float* conv_b  = (const float*)d_in[8];
    const float* skip_w  = (const float*)d_in[9];
    const float* skip_b  = (const float*)d_in[10];
    const float* fc_w    = (const float*)d_in[11];
    const float* fc_b    = (const float*)d_in[12];
    const float* loc_w   = (const float*)d_in[13];
    const float* loc_b   = (const float*)d_in[14];
    const float* scale_w = (const float*)d_in[15];
    const float* scale_b = (const float*)d_in[16];
    float* out = (float*)d_out;

    const int prepTot = NL * 3 * 512 * DH;
    prep_weights<<<(prepTot + 255) / 256, 256>>>(conv_w, skip_w);
    up_kernel<<<M_TOT, 256>>>(X_lag, X_cov, up_w, up_b);
    for (int i = 0; i < NL; i++) {
        conv_mma<<<dim3(4, 512), 256>>>(i, 1 << i, conv_b);
        skip_mma<<<dim3(4, 512), 256>>>(i, skip_b);
    }
    final_k<<<OUTL * B_SZ, 256>>>(y, fc_w, fc_b, loc_w, loc_b, scale_w, scale_b, out);
    finish_k<<<1, 1>>>(out);
}

// round 4
// speedup vs baseline: 2.0871x; 1.0972x over previous
#include <cuda_runtime.h>
#include <cuda_bf16.h>
#include <cstdint>
#include <math.h>

#define T_LEN 1024
#define B_SZ  64
#define DH    256
#define NL    8
#define OUTL  24
#define M_TOT (B_SZ * T_LEN)

// ---------------- device scratch -------------------------------------------
__device__ __align__(128) float          g_h   [M_TOT * DH];
__device__ __align__(128) float          g_skip[M_TOT * DH];
__device__ __align__(128) __nv_bfloat16  g_hhi [M_TOT * DH];
__device__ __align__(128) __nv_bfloat16  g_hlo [M_TOT * DH];
__device__ __align__(128) __nv_bfloat16  g_ghi [M_TOT * DH];
__device__ __align__(128) __nv_bfloat16  g_glo [M_TOT * DH];
// conv weights: [layer][tap][np=512][ic=256], np = 2*c + s (s=0: f ch c, s=1: g ch c)
__device__ __align__(128) __nv_bfloat16  g_Wc_hi[NL * 3 * 512 * DH];
__device__ __align__(128) __nv_bfloat16  g_Wc_lo[NL * 3 * 512 * DH];
// skip weights: [layer][oc=512][ic=256]
__device__ __align__(128) __nv_bfloat16  g_Ws_hi[NL * 512 * DH];
__device__ __align__(128) __nv_bfloat16  g_Ws_lo[NL * 512 * DH];
__device__ float g_loss;

// ---------------- PTX helpers ------------------------------------------------
__device__ __forceinline__ uint32_t cvta_s(const void* p) {
    uint32_t a;
    asm("{ .reg .u64 t; cvta.to.shared.u64 t, %1; cvt.u32.u64 %0, t; }" : "=r"(a) : "l"(p));
    return a;
}
__device__ __forceinline__ void ldsm4(uint32_t (&r)[4], uint32_t addr) {
    asm volatile("ldmatrix.sync.aligned.m8n8.x4.shared.b16 {%0,%1,%2,%3}, [%4];"
                 : "=r"(r[0]), "=r"(r[1]), "=r"(r[2]), "=r"(r[3]) : "r"(addr));
}
__device__ __forceinline__ void mma16816(float (&c)[4], const uint32_t (&a)[4],
                                         uint32_t b0, uint32_t b1) {
    asm volatile(
        "mma.sync.aligned.m16n8k16.row.col.f32.bf16.bf16.f32 "
        "{%0,%1,%2,%3}, {%4,%5,%6,%7}, {%8,%9}, {%0,%1,%2,%3};"
        : "+f"(c[0]), "+f"(c[1]), "+f"(c[2]), "+f"(c[3])
        : "r"(a[0]), "r"(a[1]), "r"(a[2]), "r"(a[3]), "r"(b0), "r"(b1));
}
__device__ __forceinline__ void cp16(uint32_t saddr, const void* g, bool pred) {
    int sz = pred ? 16 : 0;
    asm volatile("cp.async.cg.shared.global [%0], [%1], 16, %2;"
                 :: "r"(saddr), "l"(g), "r"(sz) : "memory");
}
#define CP_COMMIT() asm volatile("cp.async.commit_group;" ::: "memory")
#define CP_WAIT1()  asm volatile("cp.async.wait_group 1;" ::: "memory")
#define CP_WAIT0()  asm volatile("cp.async.wait_group 0;" ::: "memory")

// smem: per stage, 4 planes (A_hi, A_lo, B_hi, B_lo), 128 rows x 32 bf16, stride 80B
#define PL_SZ 10240
#define ROW_B 80
#define STG_SZ (4 * PL_SZ)
#define SMEM_DYN (2 * STG_SZ)

// ---------------- weight pack + init -----------------------------------------
__global__ void prep_weights(const float* __restrict__ conv_w,
                             const float* __restrict__ skip_w) {
    int idx = blockIdx.x * blockDim.x + threadIdx.x;
    if (idx == 0) g_loss = 0.0f;
    const int totC = NL * 3 * 512 * DH;
    if (idx < totC) {
        int ic = idx & 255;
        int np = (idx >> 8) & 511;
        int tap = (idx >> 17) % 3;
        int layer = idx / (3 * 512 * 256);
        int c = np >> 1, s = np & 1;
        int oc = c + s * 256;
        float v = conv_w[((size_t)(layer * 512 + oc) * DH + ic) * 3 + tap];
        __nv_bfloat16 hi = __float2bfloat16(v);
        g_Wc_hi[idx] = hi;
        g_Wc_lo[idx] = __float2bfloat16(v - __bfloat162float(hi));
    }
    const int totS = NL * 512 * DH;
    if (idx < totS) {
        float v = skip_w[idx];
        __nv_bfloat16 hi = __float2bfloat16(v);
        g_Ws_hi[idx] = hi;
        g_Ws_lo[idx] = __float2bfloat16(v - __bfloat162float(hi));
    }
}

// ---------------- up projection -----------------------------------------------
__global__ __launch_bounds__(256) void up_kernel(
    const float* __restrict__ X_lag, const float* __restrict__ X_cov,
    const float* __restrict__ up_w, const float* __restrict__ up_b) {
    int r = blockIdx.x;
    int b = r / T_LEN;
    int t = r % T_LEN;
    __shared__ float x[16];
    int c = threadIdx.x;
    if (c < 8)       x[c] = X_lag[((size_t)t * B_SZ + b) * 8 + c];
    else if (c < 16) x[c] = X_cov[((size_t)t * B_SZ + b) * 8 + (c - 8)];
    __syncthreads();
    float acc = up_b[c];
#pragma unroll
    for (int j = 0; j < 16; j++) acc += x[j] * up_w[j * DH + c];
    size_t o = (size_t)r * DH + c;
    g_h[o] = acc;
    __nv_bfloat16 hi = __float2bfloat16(acc);
    g_hhi[o] = hi;
    g_hlo[o] = __float2bfloat16(acc - __bfloat162float(hi));
}

// ---------------- conv gated HMMA kernel (cp.async pipelined) -----------------
// grid (4, 512): x = N-tile (128 packed = 64 ch x (f,g)), y = M-tile (128 rows)
__global__ __launch_bounds__(256, 2) void conv_mma(int layer, int dil,
                                                   const float* __restrict__ conv_b) {
    extern __shared__ __align__(16) unsigned char sm[];
    const int tid = threadIdx.x, wid = tid >> 5, lid = tid & 31;
    const int wm = wid & 1, wn = wid >> 1;
    const int n0 = blockIdx.x * 128, m0 = blockIdx.y * 128;
    const int t0 = m0 & (T_LEN - 1);
    const uint32_t smb = cvta_s(sm);
    const int lrow = lid & 15, lcolb = (lid >> 4) * 16;
    const int ldr = tid >> 2, ldc = (tid & 3) * 16;   // load row / byte col
    const size_t lgo = (size_t)ldr * DH + (tid & 3) * 8;

    float acc[4][4][4];
#pragma unroll
    for (int a = 0; a < 4; a++)
#pragma unroll
        for (int b = 0; b < 4; b++)
#pragma unroll
            for (int d = 0; d < 4; d++) acc[a][b][d] = 0.0f;

    const int NIT = 24;
    auto issue = [&](int it) {
        int tap = it >> 3, kc = it & 7;
        int kk = kc * 32;
        int off = (2 - tap) * dil;
        bool predA0 = (t0 + ldr) >= off;
        bool predA1 = (t0 + 64 + ldr) >= off;
        const __nv_bfloat16* Ab = g_hhi + ((long)(m0 - off) * DH + kk) + lgo;
        const __nv_bfloat16* Al = g_hlo + ((long)(m0 - off) * DH + kk) + lgo;
        const __nv_bfloat16* Bh = g_Wc_hi + ((size_t)(layer * 3 + tap) * 512 + n0) * DH + kk + lgo;
        const __nv_bfloat16* Bl = g_Wc_lo + ((size_t)(layer * 3 + tap) * 512 + n0) * DH + kk + lgo;
        uint32_t sb = smb + (it & 1) * STG_SZ + ldr * ROW_B + ldc;
        cp16(sb,                           Ab,                predA0);
        cp16(sb + 64 * ROW_B,              Ab + 64 * DH,      predA1);
        cp16(sb + PL_SZ,                   Al,                predA0);
        cp16(sb + PL_SZ + 64 * ROW_B,      Al + 64 * DH,      predA1);
        cp16(sb + 2 * PL_SZ,               Bh,                true);
        cp16(sb + 2 * PL_SZ + 64 * ROW_B,  Bh + 64 * DH,      true);
        cp16(sb + 3 * PL_SZ,               Bl,                true);
        cp16(sb + 3 * PL_SZ + 64 * ROW_B,  Bl + 64 * DH,      true);
        CP_COMMIT();
    };

    issue(0);
    for (int it = 0; it < NIT; it++) {
        if (it + 1 < NIT) { issue(it + 1); CP_WAIT1(); }
        else              { CP_WAIT0(); }
        __syncthreads();
        uint32_t s0 = smb + (it & 1) * STG_SZ;
#pragma unroll
        for (int ks = 0; ks < 2; ks++) {
            uint32_t a[4][4], bH[2][4], bL[2][4];
#pragma unroll
            for (int q = 0; q < 2; q++) {
                uint32_t bd = s0 + 2 * PL_SZ + (wn * 32 + q * 16 + lrow) * ROW_B
                            + ks * 32 + lcolb;
                ldsm4(bH[q], bd);
                ldsm4(bL[q], bd + PL_SZ);
            }
#pragma unroll
            for (int mt = 0; mt < 4; mt++)
                ldsm4(a[mt], s0 + (wm * 64 + mt * 16 + lrow) * ROW_B + ks * 32 + lcolb);
#pragma unroll
            for (int mt = 0; mt < 4; mt++)
#pragma unroll
                for (int nt = 0; nt < 4; nt++) {
                    int q = nt >> 1, h = nt & 1;
                    mma16816(acc[mt][nt], a[mt], bH[q][h], bH[q][h + 2]);
                    mma16816(acc[mt][nt], a[mt], bL[q][h], bL[q][h + 2]);
                }
#pragma unroll
            for (int mt = 0; mt < 4; mt++)
                ldsm4(a[mt], s0 + PL_SZ + (wm * 64 + mt * 16 + lrow) * ROW_B
                            + ks * 32 + lcolb);
#pragma unroll
            for (int mt = 0; mt < 4; mt++)
#pragma unroll
                for (int nt = 0; nt < 4; nt++) {
                    int q = nt >> 1, h = nt & 1;
                    mma16816(acc[mt][nt], a[mt], bH[q][h], bH[q][h + 2]);
                }
        }
        __syncthreads();
    }

    // epilogue: lane cols are (f,g) of one channel
    const float* cbf = conv_b + layer * 512;
    const int lm = lid >> 2, ln = lid & 3;
#pragma unroll
    for (int mt = 0; mt < 4; mt++) {
        int row0 = m0 + wm * 64 + mt * 16 + lm;
#pragma unroll
        for (int nt = 0; nt < 4; nt++) {
            int ch = ((n0 + wn * 32 + nt * 8) >> 1) + ln;
            float fb = __ldg(cbf + ch), gb = __ldg(cbf + 256 + ch);
#pragma unroll
            for (int u = 0; u < 2; u++) {
                int row = row0 + u * 8;
                float f = acc[mt][nt][2 * u] + fb;
                float g = acc[mt][nt][2 * u + 1] + gb;
                float e2f = __expf(2.0f * f);
                float th = (e2f - 1.0f) / (e2f + 1.0f);
                float val = th / (1.0f + __expf(-g));
                __nv_bfloat16 hi = __float2bfloat16(val);
                g_ghi[(size_t)row * DH + ch] = hi;
                g_glo[(size_t)row * DH + ch] = __float2bfloat16(val - __bfloat162float(hi));
            }
        }
    }
}

// ---------------- skip projection HMMA kernel (cp.async pipelined) ------------
__global__ __launch_bounds__(256, 2) void skip_mma(int layer,
                                                   const float* __restrict__ skip_b) {
    extern __shared__ __align__(16) unsigned char sm[];
    const int tid = threadIdx.x, wid = tid >> 5, lid = tid & 31;
    const int wm = wid & 1, wn = wid >> 1;
    const int n0 = blockIdx.x * 128, m0 = blockIdx.y * 128;
    const uint32_t smb = cvta_s(sm);
    const int lrow = lid & 15, lcolb = (lid >> 4) * 16;
    const int ldr = tid >> 2, ldc = (tid & 3) * 16;
    const size_t lgo = (size_t)ldr * DH + (tid & 3) * 8;

    float acc[4][4][4];
#pragma unroll
    for (int a = 0; a < 4; a++)
#pragma unroll
        for (int b = 0; b < 4; b++)
#pragma unroll
            for (int d = 0; d < 4; d++) acc[a][b][d] = 0.0f;

    const __nv_bfloat16* Ah = g_ghi + (size_t)m0 * DH + lgo;
    const __nv_bfloat16* Al = g_glo + (size_t)m0 * DH + lgo;
    const __nv_bfloat16* Bh = g_Ws_hi + ((size_t)layer * 512 + n0) * DH + lgo;
    const __nv_bfloat16* Bl = g_Ws_lo + ((size_t)layer * 512 + n0) * DH + lgo;

    const int NIT = 8;
    auto issue = [&](int it) {
        int kk = it * 32;
        uint32_t sb = smb + (it & 1) * STG_SZ + ldr * ROW_B + ldc;
        cp16(sb,                          Ah + kk,           true);
        cp16(sb + 64 * ROW_B,             Ah + kk + 64 * DH, true);
        cp16(sb + PL_SZ,                  Al + kk,           true);
        cp16(sb + PL_SZ + 64 * ROW_B,     Al + kk + 64 * DH, true);
        cp16(sb + 2 * PL_SZ,              Bh + kk,           true);
        cp16(sb + 2 * PL_SZ + 64 * ROW_B, Bh + kk + 64 * DH, true);
        cp16(sb + 3 * PL_SZ,              Bl + kk,           true);
        cp16(sb + 3 * PL_SZ + 64 * ROW_B, Bl + kk + 64 * DH, true);
        CP_COMMIT();
    };

    issue(0);
    for (int it = 0; it < NIT; it++) {
        if (it + 1 < NIT) { issue(it + 1); CP_WAIT1(); }
        else              { CP_WAIT0(); }
        __syncthreads();
        uint32_t s0 = smb + (it & 1) * STG_SZ;
#pragma unroll
        for (int ks = 0; ks < 2; ks++) {
            uint32_t a[4][4], bH[2][4], bL[2][4];
#pragma unroll
            for (int q = 0; q < 2; q++) {
                uint32_t bd = s0 + 2 * PL_SZ + (wn * 32 + q * 16 + lrow) * ROW_B
                            + ks * 32 + lcolb;
                ldsm4(bH[q], bd);
                ldsm4(bL[q], bd + PL_SZ);
            }
#pragma unroll
            for (int mt = 0; mt < 4; mt++)
                ldsm4(a[mt], s0 + (wm * 64 + mt * 16 + lrow) * ROW_B + ks * 32 + lcolb);
#pragma unroll
            for (int mt = 0; mt < 4; mt++)
#pragma unroll
                for (int nt = 0; nt < 4; nt++) {
                    int q = nt >> 1, h = nt & 1;
                    mma16816(acc[mt][nt], a[mt], bH[q][h], bH[q][h + 2]);
                    mma16816(acc[mt][nt], a[mt], bL[q][h], bL[q][h + 2]);
                }
#pragma unroll
            for (int mt = 0; mt < 4; mt++)
                ldsm4(a[mt], s0 + PL_SZ + (wm * 64 + mt * 16 + lrow) * ROW_B
                            + ks * 32 + lcolb);
#pragma unroll
            for (int mt = 0; mt < 4; mt++)
#pragma unroll
                for (int nt = 0; nt < 4; nt++) {
                    int q = nt >> 1, h = nt & 1;
                    mma16816(acc[mt][nt], a[mt], bH[q][h], bH[q][h + 2]);
                }
        }
        __syncthreads();
    }

    // epilogue
    const float* sb_ = skip_b + layer * 512;
    const int lm = lid >> 2, ln = lid & 3;
    const bool is_h = (n0 < 256);
#pragma unroll
    for (int mt = 0; mt < 4; mt++) {
        int row0 = m0 + wm * 64 + mt * 16 + lm;
#pragma unroll
        for (int nt = 0; nt < 4; nt++) {
            int oc = n0 + wn * 32 + nt * 8 + 2 * ln;
            float b0 = __ldg(sb_ + oc), b1 = __ldg(sb_ + oc + 1);
#pragma unroll
            for (int u = 0; u < 2; u++) {
                int row = row0 + u * 8;
                float v0 = acc[mt][nt][2 * u] + b0;
                float v1 = acc[mt][nt][2 * u + 1] + b1;
                if (is_h) {
                    float2* hp = (float2*)(g_h + (size_t)row * DH + oc);
                    float2 cur = *hp;
                    float nh0 = cur.x + v0, nh1 = cur.y + v1;
                    *hp = make_float2(nh0, nh1);
                    __nv_bfloat16 a0 = __float2bfloat16(nh0);
                    __nv_bfloat16 a1 = __float2bfloat16(nh1);
                    *(__nv_bfloat162*)(g_hhi + (size_t)row * DH + oc) = __nv_bfloat162(a0, a1);
                    *(__nv_bfloat162*)(g_hlo + (size_t)row * DH + oc) = __nv_bfloat162(
                        __float2bfloat16(nh0 - __bfloat162float(a0)),
                        __float2bfloat16(nh1 - __bfloat162float(a1)));
                } else {
                    float2* sp = (float2*)(g_skip + (size_t)row * DH + (oc - 256));
                    float2 prev = (layer == 0) ? make_float2(0.f, 0.f) : *sp;
                    *sp = make_float2(prev.x + v0, prev.y + v1);
                }
            }
        }
    }
}

// ---------------- FC head + Gaussian NLL ------------------------------------
__global__ __launch_bounds__(256) void final_k(
    const float* __restrict__ y,
    const float* __restrict__ fc_w, const float* __restrict__ fc_b,
    const float* __restrict__ loc_w, const float* __restrict__ loc_b,
    const float* __restrict__ scale_w, const float* __restrict__ scale_b,
    float* __restrict__ out) {
    int row = blockIdx.x;
    int tt = row >> 6;
    int b = row & 63;
    int t = T_LEN - OUTL + tt;
    size_t r = (size_t)b * T_LEN + t;
    __shared__ float srow[DH];
    __shared__ float red[256];
    int c = threadIdx.x;
    srow[c] = g_skip[r * DH + c];
    __syncthreads();
    float acc = fc_b[c];
#pragma unroll 8
    for (int k = 0; k < DH; k++) acc += srow[k] * fc_w[k * DH + c];
    float ff = fmaxf(acc, 0.0f);

    red[c] = ff * loc_w[c];
    __syncthreads();
    for (int s = 128; s > 0; s >>= 1) {
        if (c < s) red[c] += red[c + s];
        __syncthreads();
    }
    float loc = red[0] + loc_b[0];
    __syncthreads();

    red[c] = ff * scale_w[c];
    __syncthreads();
    for (int s = 128; s > 0; s >>= 1) {
        if (c < s) red[c] += red[c + s];
        __syncthreads();
    }
    if (c == 0) {
        float sraw = red[0] + scale_b[0];
        float sp = (sraw > 20.0f) ? sraw : log1pf(expf(sraw));
        float scale = sp + 1e-6f;
        float yt = y[(size_t)t * B_SZ + b];
        float z = (yt - loc) / scale;
        float lp = -0.5f * z * z - logf(scale) - 0.91893853320467274f;
        out[2 + row] = loc;
        out[2 + OUTL * B_SZ + row] = scale;
        atomicAdd(&g_loss, lp);
    }
}

__global__ void finish_k(float* __restrict__ out) {
    float L = -g_loss / (float)(OUTL * B_SZ);
    out[0] = L;
    out[1] = L;
}

// ---------------- launch -----------------------------------------------------
extern "C" void kernel_launch(void* const* d_in, const int* in_sizes, int n_in,
                              void* d_out, int out_size) {
    const float* X_cov   = (const float*)d_in[1];
    const float* X_lag   = (const float*)d_in[2];
    const float* y       = (const float*)d_in[3];
    const float* up_w    = (const float*)d_in[5];
    const float* up_b    = (const float*)d_in[6];
    const float* conv_w  = (const float*)d_in[7];
    const float* conv_b  = (const float*)d_in[8];
    const float* skip_w  = (const float*)d_in[9];
    const float* skip_b  = (const float*)d_in[10];
    const float* fc_w    = (const float*)d_in[11];
    const float* fc_b    = (const float*)d_in[12];
    const float* loc_w   = (const float*)d_in[13];
    const float* loc_b   = (const float*)d_in[14];
    const float* scale_w = (const float*)d_in[15];
    const float* scale_b = (const float*)d_in[16];
    float* out = (float*)d_out;

    cudaFuncSetAttribute(conv_mma, cudaFuncAttributeMaxDynamicSharedMemorySize, SMEM_DYN);
    cudaFuncSetAttribute(skip_mma, cudaFuncAttributeMaxDynamicSharedMemorySize, SMEM_DYN);

    const int prepTot = NL * 3 * 512 * DH;
    prep_weights<<<(prepTot + 255) / 256, 256>>>(conv_w, skip_w);
    up_kernel<<<M_TOT, 256>>>(X_lag, X_cov, up_w, up_b);
    for (int i = 0; i < NL; i++) {
        conv_mma<<<dim3(4, 512), 256, SMEM_DYN>>>(i, 1 << i, conv_b);
        skip_mma<<<dim3(4, 512), 256, SMEM_DYN>>>(i, skip_b);
    }
    final_k<<<OUTL * B_SZ, 256>>>(y, fc_w, fc_b, loc_w, loc_b, scale_w, scale_b, out);
    finish_k<<<1, 1>>>(out);
}

// round 5
// speedup vs baseline: 2.3180x; 1.1107x over previous
#include <cuda_runtime.h>
#include <cuda_bf16.h>
#include <cstdint>
#include <math.h>

#define T_LEN 1024
#define B_SZ  64
#define DH    256
#define NL    8
#define OUTL  24
#define M_TOT (B_SZ * T_LEN)

// ---------------- device scratch -------------------------------------------
__device__ __align__(128) float          g_h   [M_TOT * DH];
__device__ __align__(128) float          g_skip[M_TOT * DH];
__device__ __align__(128) __nv_bfloat16  g_hhi [M_TOT * DH];
__device__ __align__(128) __nv_bfloat16  g_hlo [M_TOT * DH];
__device__ __align__(128) __nv_bfloat16  g_ghi [M_TOT * DH];
__device__ __align__(128) __nv_bfloat16  g_glo [M_TOT * DH];
// conv weights: [layer][tap][np=512][ic=256], np = 2*c + s (s=0: f ch c, s=1: g ch c)
__device__ __align__(128) __nv_bfloat16  g_Wc_hi[NL * 3 * 512 * DH];
__device__ __align__(128) __nv_bfloat16  g_Wc_lo[NL * 3 * 512 * DH];
// skip weights: [layer][oc=512][ic=256]
__device__ __align__(128) __nv_bfloat16  g_Ws_hi[NL * 512 * DH];
__device__ __align__(128) __nv_bfloat16  g_Ws_lo[NL * 512 * DH];
__device__ float g_loss;

// ---------------- PTX helpers ------------------------------------------------
__device__ __forceinline__ uint32_t cvta_s(const void* p) {
    uint32_t a;
    asm("{ .reg .u64 t; cvta.to.shared.u64 t, %1; cvt.u32.u64 %0, t; }" : "=r"(a) : "l"(p));
    return a;
}
__device__ __forceinline__ void ldsm4(uint32_t (&r)[4], uint32_t addr) {
    asm volatile("ldmatrix.sync.aligned.m8n8.x4.shared.b16 {%0,%1,%2,%3}, [%4];"
                 : "=r"(r[0]), "=r"(r[1]), "=r"(r[2]), "=r"(r[3]) : "r"(addr));
}
__device__ __forceinline__ void mma16816(float (&c)[4], const uint32_t (&a)[4],
                                         uint32_t b0, uint32_t b1) {
    asm volatile(
        "mma.sync.aligned.m16n8k16.row.col.f32.bf16.bf16.f32 "
        "{%0,%1,%2,%3}, {%4,%5,%6,%7}, {%8,%9}, {%0,%1,%2,%3};"
        : "+f"(c[0]), "+f"(c[1]), "+f"(c[2]), "+f"(c[3])
        : "r"(a[0]), "r"(a[1]), "r"(a[2]), "r"(a[3]), "r"(b0), "r"(b1));
}
__device__ __forceinline__ void cp16(uint32_t saddr, const void* g, bool pred) {
    int sz = pred ? 16 : 0;
    asm volatile("cp.async.cg.shared.global [%0], [%1], 16, %2;"
                 :: "r"(saddr), "l"(g), "r"(sz) : "memory");
}
#define CP_COMMIT() asm volatile("cp.async.commit_group;" ::: "memory")
#define CP_WAIT1()  asm volatile("cp.async.wait_group 1;" ::: "memory")
#define CP_WAIT0()  asm volatile("cp.async.wait_group 0;" ::: "memory")

// Stage layout: superplane A @0 (128 rows x 128B = [hi 64B | lo 64B], SW128 swizzled),
//               superplane B @16KB. Stage = 32KB, 2 stages = 64KB.
#define SP_B  16384
#define STG_SZ 32768
#define SMEM_DYN (2 * STG_SZ)
// chunk position swizzle: 16B chunk index c (0..7) at row r -> byte offset
#define SWA(r, c) ((uint32_t)((r) * 128 + (((c) ^ ((r) & 7)) << 4)))

// ---------------- weight pack + init -----------------------------------------
__global__ void prep_weights(const float* __restrict__ conv_w,
                             const float* __restrict__ skip_w) {
    int idx = blockIdx.x * blockDim.x + threadIdx.x;
    if (idx == 0) g_loss = 0.0f;
    const int totC = NL * 3 * 512 * DH;
    if (idx < totC) {
        int ic = idx & 255;
        int np = (idx >> 8) & 511;
        int tap = (idx >> 17) % 3;
        int layer = idx / (3 * 512 * 256);
        int c = np >> 1, s = np & 1;
        int oc = c + s * 256;
        float v = conv_w[((size_t)(layer * 512 + oc) * DH + ic) * 3 + tap];
        __nv_bfloat16 hi = __float2bfloat16(v);
        g_Wc_hi[idx] = hi;
        g_Wc_lo[idx] = __float2bfloat16(v - __bfloat162float(hi));
    }
    const int totS = NL * 512 * DH;
    if (idx < totS) {
        float v = skip_w[idx];
        __nv_bfloat16 hi = __float2bfloat16(v);
        g_Ws_hi[idx] = hi;
        g_Ws_lo[idx] = __float2bfloat16(v - __bfloat162float(hi));
    }
}

// ---------------- up projection -----------------------------------------------
__global__ __launch_bounds__(256) void up_kernel(
    const float* __restrict__ X_lag, const float* __restrict__ X_cov,
    const float* __restrict__ up_w, const float* __restrict__ up_b) {
    int r = blockIdx.x;
    int b = r / T_LEN;
    int t = r % T_LEN;
    __shared__ float x[16];
    int c = threadIdx.x;
    if (c < 8)       x[c] = X_lag[((size_t)t * B_SZ + b) * 8 + c];
    else if (c < 16) x[c] = X_cov[((size_t)t * B_SZ + b) * 8 + (c - 8)];
    __syncthreads();
    float acc = up_b[c];
#pragma unroll
    for (int j = 0; j < 16; j++) acc += x[j] * up_w[j * DH + c];
    size_t o = (size_t)r * DH + c;
    g_h[o] = acc;
    __nv_bfloat16 hi = __float2bfloat16(acc);
    g_hhi[o] = hi;
    g_hlo[o] = __float2bfloat16(acc - __bfloat162float(hi));
}

// ---------------- conv gated HMMA kernel (cp.async + SW128) -------------------
// grid (4, 512): x = N-tile (128 packed = 64 ch x (f,g)), y = M-tile (128 rows)
__global__ __launch_bounds__(256, 2) void conv_mma(int layer, int dil,
                                                   const float* __restrict__ conv_b) {
    extern __shared__ __align__(16) unsigned char sm[];
    const int tid = threadIdx.x, wid = tid >> 5, lid = tid & 31;
    const int wm = wid & 1, wn = wid >> 1;
    const int n0 = blockIdx.x * 128, m0 = blockIdx.y * 128;
    const int t0 = m0 & (T_LEN - 1);
    const uint32_t smb = cvta_s(sm);
    const int lrow = lid & 15, khalf = lid >> 4;
    const int lc = tid & 3, lislo = (tid >> 2) & 1, lrr = tid >> 3;  // loader coords

    float acc[4][4][4];
#pragma unroll
    for (int a = 0; a < 4; a++)
#pragma unroll
        for (int b = 0; b < 4; b++)
#pragma unroll
            for (int d = 0; d < 4; d++) acc[a][b][d] = 0.0f;

    const int NIT = 24;
    auto issue = [&](int it) {
        int tap = it >> 3, kc = it & 7;
        int kk = kc * 32;
        int off = (2 - tap) * dil;
        const __nv_bfloat16* Asrc = (lislo ? g_hlo : g_hhi) + ((long)(m0 - off) * DH + kk) + lc * 8;
        const __nv_bfloat16* Bsrc = (lislo ? g_Wc_lo : g_Wc_hi)
                                  + ((size_t)(layer * 3 + tap) * 512 + n0) * DH + kk + lc * 8;
        uint32_t sb = smb + (it & 1) * STG_SZ;
        int chunk = lislo * 4 + lc;
#pragma unroll
        for (int q = 0; q < 4; q++) {
            int r = q * 32 + lrr;
            uint32_t dst = sb + SWA(r, chunk);
            cp16(dst,        Asrc + (size_t)r * DH, (t0 + r) >= off);
            cp16(dst + SP_B, Bsrc + (size_t)r * DH, true);
        }
        CP_COMMIT();
    };

    issue(0);
    for (int it = 0; it < NIT; it++) {
        if (it + 1 < NIT) { issue(it + 1); CP_WAIT1(); }
        else              { CP_WAIT0(); }
        __syncthreads();
        uint32_t s0 = smb + (it & 1) * STG_SZ;
#pragma unroll
        for (int ks = 0; ks < 2; ks++) {
            int ch = 2 * ks + khalf;
            uint32_t a[4][4], bH[2][4], bL[2][4];
#pragma unroll
            for (int q = 0; q < 2; q++) {
                int rB = wn * 32 + q * 16 + lrow;
                ldsm4(bH[q], s0 + SP_B + SWA(rB, ch));
                ldsm4(bL[q], s0 + SP_B + SWA(rB, ch + 4));
            }
#pragma unroll
            for (int mt = 0; mt < 4; mt++) {
                int rA = wm * 64 + mt * 16 + lrow;
                ldsm4(a[mt], s0 + SWA(rA, ch));
            }
#pragma unroll
            for (int mt = 0; mt < 4; mt++)
#pragma unroll
                for (int nt = 0; nt < 4; nt++) {
                    int q = nt >> 1, h = nt & 1;
                    mma16816(acc[mt][nt], a[mt], bH[q][h], bH[q][h + 2]);
                    mma16816(acc[mt][nt], a[mt], bL[q][h], bL[q][h + 2]);
                }
#pragma unroll
            for (int mt = 0; mt < 4; mt++) {
                int rA = wm * 64 + mt * 16 + lrow;
                ldsm4(a[mt], s0 + SWA(rA, ch + 4));
            }
#pragma unroll
            for (int mt = 0; mt < 4; mt++)
#pragma unroll
                for (int nt = 0; nt < 4; nt++) {
                    int q = nt >> 1, h = nt & 1;
                    mma16816(acc[mt][nt], a[mt], bH[q][h], bH[q][h + 2]);
                }
        }
        __syncthreads();
    }

    // epilogue: lane cols are (f,g) of one channel
    const float* cbf = conv_b + layer * 512;
    const int lm = lid >> 2, ln = lid & 3;
#pragma unroll
    for (int mt = 0; mt < 4; mt++) {
        int row0 = m0 + wm * 64 + mt * 16 + lm;
#pragma unroll
        for (int nt = 0; nt < 4; nt++) {
            int ch = ((n0 + wn * 32 + nt * 8) >> 1) + ln;
            float fb = __ldg(cbf + ch), gb = __ldg(cbf + 256 + ch);
#pragma unroll
            for (int u = 0; u < 2; u++) {
                int row = row0 + u * 8;
                float f = acc[mt][nt][2 * u] + fb;
                float g = acc[mt][nt][2 * u + 1] + gb;
                float e2f = __expf(2.0f * f);
                float th = (e2f - 1.0f) / (e2f + 1.0f);
                float val = th / (1.0f + __expf(-g));
                __nv_bfloat16 hi = __float2bfloat16(val);
                g_ghi[(size_t)row * DH + ch] = hi;
                g_glo[(size_t)row * DH + ch] = __float2bfloat16(val - __bfloat162float(hi));
            }
        }
    }
}

// ---------------- skip projection HMMA kernel (cp.async + SW128) --------------
__global__ __launch_bounds__(256, 2) void skip_mma(int layer,
                                                   const float* __restrict__ skip_b) {
    extern __shared__ __align__(16) unsigned char sm[];
    const int tid = threadIdx.x, wid = tid >> 5, lid = tid & 31;
    const int wm = wid & 1, wn = wid >> 1;
    const int n0 = blockIdx.x * 128, m0 = blockIdx.y * 128;
    const uint32_t smb = cvta_s(sm);
    const int lrow = lid & 15, khalf = lid >> 4;
    const int lc = tid & 3, lislo = (tid >> 2) & 1, lrr = tid >> 3;

    float acc[4][4][4];
#pragma unroll
    for (int a = 0; a < 4; a++)
#pragma unroll
        for (int b = 0; b < 4; b++)
#pragma unroll
            for (int d = 0; d < 4; d++) acc[a][b][d] = 0.0f;

    const __nv_bfloat16* Asrc = (lislo ? g_glo : g_ghi) + (size_t)m0 * DH + lc * 8;
    const __nv_bfloat16* Bsrc = (lislo ? g_Ws_lo : g_Ws_hi)
                              + ((size_t)layer * 512 + n0) * DH + lc * 8;
    const int chunk = lislo * 4 + lc;

    const int NIT = 8;
    auto issue = [&](int it) {
        int kk = it * 32;
        uint32_t sb = smb + (it & 1) * STG_SZ;
#pragma unroll
        for (int q = 0; q < 4; q++) {
            int r = q * 32 + lrr;
            uint32_t dst = sb + SWA(r, chunk);
            cp16(dst,        Asrc + (size_t)r * DH + kk, true);
            cp16(dst + SP_B, Bsrc + (size_t)r * DH + kk, true);
        }
        CP_COMMIT();
    };

    issue(0);
    for (int it = 0; it < NIT; it++) {
        if (it + 1 < NIT) { issue(it + 1); CP_WAIT1(); }
        else              { CP_WAIT0(); }
        __syncthreads();
        uint32_t s0 = smb + (it & 1) * STG_SZ;
#pragma unroll
        for (int ks = 0; ks < 2; ks++) {
            int ch = 2 * ks + khalf;
            uint32_t a[4][4], bH[2][4], bL[2][4];
#pragma unroll
            for (int q = 0; q < 2; q++) {
                int rB = wn * 32 + q * 16 + lrow;
                ldsm4(bH[q], s0 + SP_B + SWA(rB, ch));
                ldsm4(bL[q], s0 + SP_B + SWA(rB, ch + 4));
            }
#pragma unroll
            for (int mt = 0; mt < 4; mt++) {
                int rA = wm * 64 + mt * 16 + lrow;
                ldsm4(a[mt], s0 + SWA(rA, ch));
            }
#pragma unroll
            for (int mt = 0; mt < 4; mt++)
#pragma unroll
                for (int nt = 0; nt < 4; nt++) {
                    int q = nt >> 1, h = nt & 1;
                    mma16816(acc[mt][nt], a[mt], bH[q][h], bH[q][h + 2]);
                    mma16816(acc[mt][nt], a[mt], bL[q][h], bL[q][h + 2]);
                }
#pragma unroll
            for (int mt = 0; mt < 4; mt++) {
                int rA = wm * 64 + mt * 16 + lrow;
                ldsm4(a[mt], s0 + SWA(rA, ch + 4));
            }
#pragma unroll
            for (int mt = 0; mt < 4; mt++)
#pragma unroll
                for (int nt = 0; nt < 4; nt++) {
                    int q = nt >> 1, h = nt & 1;
                    mma16816(acc[mt][nt], a[mt], bH[q][h], bH[q][h + 2]);
                }
        }
        __syncthreads();
    }

    // epilogue
    const float* sb_ = skip_b + layer * 512;
    const int lm = lid >> 2, ln = lid & 3;
    const bool is_h = (n0 < 256);
#pragma unroll
    for (int mt = 0; mt < 4; mt++) {
        int row0 = m0 + wm * 64 + mt * 16 + lm;
#pragma unroll
        for (int nt = 0; nt < 4; nt++) {
            int oc = n0 + wn * 32 + nt * 8 + 2 * ln;
            float b0 = __ldg(sb_ + oc), b1 = __ldg(sb_ + oc + 1);
#pragma unroll
            for (int u = 0; u < 2; u++) {
                int row = row0 + u * 8;
                float v0 = acc[mt][nt][2 * u] + b0;
                float v1 = acc[mt][nt][2 * u + 1] + b1;
                if (is_h) {
                    float2* hp = (float2*)(g_h + (size_t)row * DH + oc);
                    float2 cur = *hp;
                    float nh0 = cur.x + v0, nh1 = cur.y + v1;
                    *hp = make_float2(nh0, nh1);
                    __nv_bfloat16 a0 = __float2bfloat16(nh0);
                    __nv_bfloat16 a1 = __float2bfloat16(nh1);
                    *(__nv_bfloat162*)(g_hhi + (size_t)row * DH + oc) = __nv_bfloat162(a0, a1);
                    *(__nv_bfloat162*)(g_hlo + (size_t)row * DH + oc) = __nv_bfloat162(
                        __float2bfloat16(nh0 - __bfloat162float(a0)),
                        __float2bfloat16(nh1 - __bfloat162float(a1)));
                } else {
                    float2* sp = (float2*)(g_skip + (size_t)row * DH + (oc - 256));
                    float2 prev = (layer == 0) ? make_float2(0.f, 0.f) : *sp;
                    *sp = make_float2(prev.x + v0, prev.y + v1);
                }
            }
        }
    }
}

// ---------------- FC head + Gaussian NLL ------------------------------------
__global__ __launch_bounds__(256) void final_k(
    const float* __restrict__ y,
    const float* __restrict__ fc_w, const float* __restrict__ fc_b,
    const float* __restrict__ loc_w, const float* __restrict__ loc_b,
    const float* __restrict__ scale_w, const float* __restrict__ scale_b,
    float* __restrict__ out) {
    int row = blockIdx.x;
    int tt = row >> 6;
    int b = row & 63;
    int t = T_LEN - OUTL + tt;
    size_t r = (size_t)b * T_LEN + t;
    __shared__ float srow[DH];
    __shared__ float red[256];
    int c = threadIdx.x;
    srow[c] = g_skip[r * DH + c];
    __syncthreads();
    float acc = fc_b[c];
#pragma unroll 8
    for (int k = 0; k < DH; k++) acc += srow[k] * fc_w[k * DH + c];
    float ff = fmaxf(acc, 0.0f);

    red[c] = ff * loc_w[c];
    __syncthreads();
    for (int s = 128; s > 0; s >>= 1) {
        if (c < s) red[c] += red[c + s];
        __syncthreads();
    }
    float loc = red[0] + loc_b[0];
    __syncthreads();

    red[c] = ff * scale_w[c];
    __syncthreads();
    for (int s = 128; s > 0; s >>= 1) {
        if (c < s) red[c] += red[c + s];
        __syncthreads();
    }
    if (c == 0) {
        float sraw = red[0] + scale_b[0];
        float sp = (sraw > 20.0f) ? sraw : log1pf(expf(sraw));
        float scale = sp + 1e-6f;
        float yt = y[(size_t)t * B_SZ + b];
        float z = (yt - loc) / scale;
        float lp = -0.5f * z * z - logf(scale) - 0.91893853320467274f;
        out[2 + row] = loc;
        out[2 + OUTL * B_SZ + row] = scale;
        atomicAdd(&g_loss, lp);
    }
}

__global__ void finish_k(float* __restrict__ out) {
    float L = -g_loss / (float)(OUTL * B_SZ);
    out[0] = L;
    out[1] = L;
}

// ---------------- launch -----------------------------------------------------
extern "C" void kernel_launch(void* const* d_in, const int* in_sizes, int n_in,
                              void* d_out, int out_size) {
    const float* X_cov   = (const float*)d_in[1];
    const float* X_lag   = (const float*)d_in[2];
    const float* y       = (const float*)d_in[3];
    const float* up_w    = (const float*)d_in[5];
    const float* up_b    = (const float*)d_in[6];
    const float* conv_w  = (const float*)d_in[7];
    const float* conv_b  = (const float*)d_in[8];
    const float* skip_w  = (const float*)d_in[9];
    const float* skip_b  = (const float*)d_in[10];
    const float* fc_w    = (const float*)d_in[11];
    const float* fc_b    = (const float*)d_in[12];
    const float* loc_w   = (const float*)d_in[13];
    const float* loc_b   = (const float*)d_in[14];
    const float* scale_w = (const float*)d_in[15];
    const float* scale_b = (const float*)d_in[16];
    float* out = (float*)d_out;

    cudaFuncSetAttribute(conv_mma, cudaFuncAttributeMaxDynamicSharedMemorySize, SMEM_DYN);
    cudaFuncSetAttribute(skip_mma, cudaFuncAttributeMaxDynamicSharedMemorySize, SMEM_DYN);

    const int prepTot = NL * 3 * 512 * DH;
    prep_weights<<<(prepTot + 255) / 256, 256>>>(conv_w, skip_w);
    up_kernel<<<M_TOT, 256>>>(X_lag, X_cov, up_w, up_b);
    for (int i = 0; i < NL; i++) {
        conv_mma<<<dim3(4, 512), 256, SMEM_DYN>>>(i, 1 << i, conv_b);
        skip_mma<<<dim3(4, 512), 256, SMEM_DYN>>>(i, skip_b);
    }
    final_k<<<OUTL * B_SZ, 256>>>(y, fc_w, fc_b, loc_w, loc_b, scale_w, scale_b, out);
    finish_k<<<1, 1>>>(out);
}

// round 6
// speedup vs baseline: 2.3302x; 1.0053x over previous
#include <cuda_runtime.h>
#include <cuda_bf16.h>
#include <cstdint>
#include <math.h>

#define T_LEN 1024
#define B_SZ  64
#define DH    256
#define NL    8
#define OUTL  24
#define M_TOT (B_SZ * T_LEN)

// ---------------- device scratch -------------------------------------------
__device__ __align__(128) float          g_h   [M_TOT * DH];
__device__ __align__(128) float          g_skip[M_TOT * DH];
__device__ __align__(128) __nv_bfloat16  g_hhi [M_TOT * DH];
__device__ __align__(128) __nv_bfloat16  g_hlo [M_TOT * DH];
__device__ __align__(128) __nv_bfloat16  g_ghi [M_TOT * DH];
__device__ __align__(128) __nv_bfloat16  g_glo [M_TOT * DH];
// conv weights: [layer][tap][np=512][ic=256], np = 2*c + s (s=0: f ch c, s=1: g ch c)
__device__ __align__(128) __nv_bfloat16  g_Wc_hi[NL * 3 * 512 * DH];
__device__ __align__(128) __nv_bfloat16  g_Wc_lo[NL * 3 * 512 * DH];
// skip weights: [layer][oc=512][ic=256]
__device__ __align__(128) __nv_bfloat16  g_Ws_hi[NL * 512 * DH];
__device__ __align__(128) __nv_bfloat16  g_Ws_lo[NL * 512 * DH];
__device__ float g_loss;

// ---------------- PTX helpers ------------------------------------------------
__device__ __forceinline__ uint32_t cvta_s(const void* p) {
    uint32_t a;
    asm("{ .reg .u64 t; cvta.to.shared.u64 t, %1; cvt.u32.u64 %0, t; }" : "=r"(a) : "l"(p));
    return a;
}
__device__ __forceinline__ void ldsm4(uint32_t (&r)[4], uint32_t addr) {
    asm volatile("ldmatrix.sync.aligned.m8n8.x4.shared.b16 {%0,%1,%2,%3}, [%4];"
                 : "=r"(r[0]), "=r"(r[1]), "=r"(r[2]), "=r"(r[3]) : "r"(addr));
}
__device__ __forceinline__ void mma16816(float (&c)[4], const uint32_t (&a)[4],
                                         uint32_t b0, uint32_t b1) {
    asm volatile(
        "mma.sync.aligned.m16n8k16.row.col.f32.bf16.bf16.f32 "
        "{%0,%1,%2,%3}, {%4,%5,%6,%7}, {%8,%9}, {%0,%1,%2,%3};"
        : "+f"(c[0]), "+f"(c[1]), "+f"(c[2]), "+f"(c[3])
        : "r"(a[0]), "r"(a[1]), "r"(a[2]), "r"(a[3]), "r"(b0), "r"(b1));
}
__device__ __forceinline__ void cp16(uint32_t saddr, const void* g, bool pred) {
    int sz = pred ? 16 : 0;
    asm volatile("cp.async.cg.shared.global [%0], [%1], 16, %2;"
                 :: "r"(saddr), "l"(g), "r"(sz) : "memory");
}
#define CP_COMMIT() asm volatile("cp.async.commit_group;" ::: "memory")
#define CP_WAIT1()  asm volatile("cp.async.wait_group 1;" ::: "memory")
#define CP_WAIT0()  asm volatile("cp.async.wait_group 0;" ::: "memory")

// Stage layout: superplane A @0 (128 rows x 128B = [hi 64B | lo 64B], SW128 swizzled),
//               superplane B @16KB. Stage = 32KB, 3 stages = 96KB.
#define SP_B  16384
#define STG_SZ 32768
#define SMEM_DYN (3 * STG_SZ)
// chunk position swizzle: 16B chunk index c (0..7) at row r -> byte offset
#define SWA(r, c) ((uint32_t)((r) * 128 + (((c) ^ ((r) & 7)) << 4)))

// ---------------- weight pack + init -----------------------------------------
__global__ void prep_weights(const float* __restrict__ conv_w,
                             const float* __restrict__ skip_w) {
    int idx = blockIdx.x * blockDim.x + threadIdx.x;
    if (idx == 0) g_loss = 0.0f;
    const int totC = NL * 3 * 512 * DH;
    if (idx < totC) {
        int ic = idx & 255;
        int np = (idx >> 8) & 511;
        int tap = (idx >> 17) % 3;
        int layer = idx / (3 * 512 * 256);
        int c = np >> 1, s = np & 1;
        int oc = c + s * 256;
        float v = conv_w[((size_t)(layer * 512 + oc) * DH + ic) * 3 + tap];
        __nv_bfloat16 hi = __float2bfloat16(v);
        g_Wc_hi[idx] = hi;
        g_Wc_lo[idx] = __float2bfloat16(v - __bfloat162float(hi));
    }
    const int totS = NL * 512 * DH;
    if (idx < totS) {
        float v = skip_w[idx];
        __nv_bfloat16 hi = __float2bfloat16(v);
        g_Ws_hi[idx] = hi;
        g_Ws_lo[idx] = __float2bfloat16(v - __bfloat162float(hi));
    }
}

// ---------------- up projection -----------------------------------------------
__global__ __launch_bounds__(256) void up_kernel(
    const float* __restrict__ X_lag, const float* __restrict__ X_cov,
    const float* __restrict__ up_w, const float* __restrict__ up_b) {
    int r = blockIdx.x;
    int b = r / T_LEN;
    int t = r % T_LEN;
    __shared__ float x[16];
    int c = threadIdx.x;
    if (c < 8)       x[c] = X_lag[((size_t)t * B_SZ + b) * 8 + c];
    else if (c < 16) x[c] = X_cov[((size_t)t * B_SZ + b) * 8 + (c - 8)];
    __syncthreads();
    float acc = up_b[c];
#pragma unroll
    for (int j = 0; j < 16; j++) acc += x[j] * up_w[j * DH + c];
    size_t o = (size_t)r * DH + c;
    g_h[o] = acc;
    __nv_bfloat16 hi = __float2bfloat16(acc);
    g_hhi[o] = hi;
    g_hlo[o] = __float2bfloat16(acc - __bfloat162float(hi));
}

// ---------------- conv gated HMMA kernel (3-stage cp.async + SW128) -----------
// grid (4, 512): x = N-tile (128 packed = 64 ch x (f,g)), y = M-tile (128 rows)
__global__ __launch_bounds__(256, 2) void conv_mma(int layer, int dil,
                                                   const float* __restrict__ conv_b) {
    extern __shared__ __align__(16) unsigned char sm[];
    const int tid = threadIdx.x, wid = tid >> 5, lid = tid & 31;
    const int wm = wid & 1, wn = wid >> 1;
    const int n0 = blockIdx.x * 128, m0 = blockIdx.y * 128;
    const int t0 = m0 & (T_LEN - 1);
    const uint32_t smb = cvta_s(sm);
    const int lrow = lid & 15, khalf = lid >> 4;
    const int lc = tid & 3, lislo = (tid >> 2) & 1, lrr = tid >> 3;  // loader coords

    float acc[4][4][4];
#pragma unroll
    for (int a = 0; a < 4; a++)
#pragma unroll
        for (int b = 0; b < 4; b++)
#pragma unroll
            for (int d = 0; d < 4; d++) acc[a][b][d] = 0.0f;

    const int NIT = 24;
    const int chunk = lislo * 4 + lc;
    auto issue = [&](int it) {
        int tap = it >> 3, kc = it & 7;
        int kk = kc * 32;
        int off = (2 - tap) * dil;
        const __nv_bfloat16* Asrc = (lislo ? g_hlo : g_hhi) + ((long)(m0 - off) * DH + kk) + lc * 8;
        const __nv_bfloat16* Bsrc = (lislo ? g_Wc_lo : g_Wc_hi)
                                  + ((size_t)(layer * 3 + tap) * 512 + n0) * DH + kk + lc * 8;
        uint32_t sb = smb + (it % 3) * STG_SZ;
#pragma unroll
        for (int q = 0; q < 4; q++) {
            int r = q * 32 + lrr;
            uint32_t dst = sb + SWA(r, chunk);
            cp16(dst,        Asrc + (size_t)r * DH, (t0 + r) >= off);
            cp16(dst + SP_B, Bsrc + (size_t)r * DH, true);
        }
        CP_COMMIT();
    };

    issue(0);
    issue(1);
    for (int it = 0; it < NIT; it++) {
        if (it + 1 < NIT) CP_WAIT1(); else CP_WAIT0();
        __syncthreads();
        if (it + 2 < NIT) issue(it + 2);
        uint32_t s0 = smb + (it % 3) * STG_SZ;
#pragma unroll
        for (int ks = 0; ks < 2; ks++) {
            int ch = 2 * ks + khalf;
            uint32_t a[4][4], bH[2][4], bL[2][4];
#pragma unroll
            for (int q = 0; q < 2; q++) {
                int rB = wn * 32 + q * 16 + lrow;
                ldsm4(bH[q], s0 + SP_B + SWA(rB, ch));
                ldsm4(bL[q], s0 + SP_B + SWA(rB, ch + 4));
            }
#pragma unroll
            for (int mt = 0; mt < 4; mt++) {
                int rA = wm * 64 + mt * 16 + lrow;
                ldsm4(a[mt], s0 + SWA(rA, ch));
            }
#pragma unroll
            for (int mt = 0; mt < 4; mt++)
#pragma unroll
                for (int nt = 0; nt < 4; nt++) {
                    int q = nt >> 1, h = nt & 1;
                    mma16816(acc[mt][nt], a[mt], bH[q][h], bH[q][h + 2]);
                    mma16816(acc[mt][nt], a[mt], bL[q][h], bL[q][h + 2]);
                }
#pragma unroll
            for (int mt = 0; mt < 4; mt++) {
                int rA = wm * 64 + mt * 16 + lrow;
                ldsm4(a[mt], s0 + SWA(rA, ch + 4));
            }
#pragma unroll
            for (int mt = 0; mt < 4; mt++)
#pragma unroll
                for (int nt = 0; nt < 4; nt++) {
                    int q = nt >> 1, h = nt & 1;
                    mma16816(acc[mt][nt], a[mt], bH[q][h], bH[q][h + 2]);
                }
        }
    }

    // epilogue: lane cols are (f,g) of one channel
    const float* cbf = conv_b + layer * 512;
    const int lm = lid >> 2, ln = lid & 3;
#pragma unroll
    for (int mt = 0; mt < 4; mt++) {
        int row0 = m0 + wm * 64 + mt * 16 + lm;
#pragma unroll
        for (int nt = 0; nt < 4; nt++) {
            int ch = ((n0 + wn * 32 + nt * 8) >> 1) + ln;
            float fb = __ldg(cbf + ch), gb = __ldg(cbf + 256 + ch);
#pragma unroll
            for (int u = 0; u < 2; u++) {
                int row = row0 + u * 8;
                float f = acc[mt][nt][2 * u] + fb;
                float g = acc[mt][nt][2 * u + 1] + gb;
                float e2f = __expf(2.0f * f);
                float th = (e2f - 1.0f) / (e2f + 1.0f);
                float val = th / (1.0f + __expf(-g));
                __nv_bfloat16 hi = __float2bfloat16(val);
                g_ghi[(size_t)row * DH + ch] = hi;
                g_glo[(size_t)row * DH + ch] = __float2bfloat16(val - __bfloat162float(hi));
            }
        }
    }
}

// ---------------- skip projection HMMA kernel (3-stage cp.async + SW128) -------
__global__ __launch_bounds__(256, 2) void skip_mma(int layer,
                                                   const float* __restrict__ skip_b) {
    extern __shared__ __align__(16) unsigned char sm[];
    const int tid = threadIdx.x, wid = tid >> 5, lid = tid & 31;
    const int wm = wid & 1, wn = wid >> 1;
    const int n0 = blockIdx.x * 128, m0 = blockIdx.y * 128;
    const uint32_t smb = cvta_s(sm);
    const int lrow = lid & 15, khalf = lid >> 4;
    const int lc = tid & 3, lislo = (tid >> 2) & 1, lrr = tid >> 3;

    float acc[4][4][4];
#pragma unroll
    for (int a = 0; a < 4; a++)
#pragma unroll
        for (int b = 0; b < 4; b++)
#pragma unroll
            for (int d = 0; d < 4; d++) acc[a][b][d] = 0.0f;

    const __nv_bfloat16* Asrc = (lislo ? g_glo : g_ghi) + (size_t)m0 * DH + lc * 8;
    const __nv_bfloat16* Bsrc = (lislo ? g_Ws_lo : g_Ws_hi)
                              + ((size_t)layer * 512 + n0) * DH + lc * 8;
    const int chunk = lislo * 4 + lc;

    const int NIT = 8;
    auto issue = [&](int it) {
        int kk = it * 32;
        uint32_t sb = smb + (it % 3) * STG_SZ;
#pragma unroll
        for (int q = 0; q < 4; q++) {
            int r = q * 32 + lrr;
            uint32_t dst = sb + SWA(r, chunk);
            cp16(dst,        Asrc + (size_t)r * DH + kk, true);
            cp16(dst + SP_B, Bsrc + (size_t)r * DH + kk, true);
        }
        CP_COMMIT();
    };

    issue(0);
    issue(1);
    for (int it = 0; it < NIT; it++) {
        if (it + 1 < NIT) CP_WAIT1(); else CP_WAIT0();
        __syncthreads();
        if (it + 2 < NIT) issue(it + 2);
        uint32_t s0 = smb + (it % 3) * STG_SZ;
#pragma unroll
        for (int ks = 0; ks < 2; ks++) {
            int ch = 2 * ks + khalf;
            uint32_t a[4][4], bH[2][4], bL[2][4];
#pragma unroll
            for (int q = 0; q < 2; q++) {
                int rB = wn * 32 + q * 16 + lrow;
                ldsm4(bH[q], s0 + SP_B + SWA(rB, ch));
                ldsm4(bL[q], s0 + SP_B + SWA(rB, ch + 4));
            }
#pragma unroll
            for (int mt = 0; mt < 4; mt++) {
                int rA = wm * 64 + mt * 16 + lrow;
                ldsm4(a[mt], s0 + SWA(rA, ch));
            }
#pragma unroll
            for (int mt = 0; mt < 4; mt++)
#pragma unroll
                for (int nt = 0; nt < 4; nt++) {
                    int q = nt >> 1, h = nt & 1;
                    mma16816(acc[mt][nt], a[mt], bH[q][h], bH[q][h + 2]);
                    mma16816(acc[mt][nt], a[mt], bL[q][h], bL[q][h + 2]);
                }
#pragma unroll
            for (int mt = 0; mt < 4; mt++) {
                int rA = wm * 64 + mt * 16 + lrow;
                ldsm4(a[mt], s0 + SWA(rA, ch + 4));
            }
#pragma unroll
            for (int mt = 0; mt < 4; mt++)
#pragma unroll
                for (int nt = 0; nt < 4; nt++) {
                    int q = nt >> 1, h = nt & 1;
                    mma16816(acc[mt][nt], a[mt], bH[q][h], bH[q][h + 2]);
                }
        }
    }

    // epilogue
    const float* sb_ = skip_b + layer * 512;
    const int lm = lid >> 2, ln = lid & 3;
    const bool is_h = (n0 < 256);
#pragma unroll
    for (int mt = 0; mt < 4; mt++) {
        int row0 = m0 + wm * 64 + mt * 16 + lm;
#pragma unroll
        for (int nt = 0; nt < 4; nt++) {
            int oc = n0 + wn * 32 + nt * 8 + 2 * ln;
            float b0 = __ldg(sb_ + oc), b1 = __ldg(sb_ + oc + 1);
#pragma unroll
            for (int u = 0; u < 2; u++) {
                int row = row0 + u * 8;
                float v0 = acc[mt][nt][2 * u] + b0;
                float v1 = acc[mt][nt][2 * u + 1] + b1;
                if (is_h) {
                    float2* hp = (float2*)(g_h + (size_t)row * DH + oc);
                    float2 cur = *hp;
                    float nh0 = cur.x + v0, nh1 = cur.y + v1;
                    *hp = make_float2(nh0, nh1);
                    __nv_bfloat16 a0 = __float2bfloat16(nh0);
                    __nv_bfloat16 a1 = __float2bfloat16(nh1);
                    *(__nv_bfloat162*)(g_hhi + (size_t)row * DH + oc) = __nv_bfloat162(a0, a1);
                    *(__nv_bfloat162*)(g_hlo + (size_t)row * DH + oc) = __nv_bfloat162(
                        __float2bfloat16(nh0 - __bfloat162float(a0)),
                        __float2bfloat16(nh1 - __bfloat162float(a1)));
                } else {
                    float2* sp = (float2*)(g_skip + (size_t)row * DH + (oc - 256));
                    float2 prev = (layer == 0) ? make_float2(0.f, 0.f) : *sp;
                    *sp = make_float2(prev.x + v0, prev.y + v1);
                }
            }
        }
    }
}

// ---------------- FC head + Gaussian NLL ------------------------------------
__global__ __launch_bounds__(256) void final_k(
    const float* __restrict__ y,
    const float* __restrict__ fc_w, const float* __restrict__ fc_b,
    const float* __restrict__ loc_w, const float* __restrict__ loc_b,
    const float* __restrict__ scale_w, const float* __restrict__ scale_b,
    float* __restrict__ out) {
    int row = blockIdx.x;
    int tt = row >> 6;
    int b = row & 63;
    int t = T_LEN - OUTL + tt;
    size_t r = (size_t)b * T_LEN + t;
    __shared__ float srow[DH];
    __shared__ float red[256];
    int c = threadIdx.x;
    srow[c] = g_skip[r * DH + c];
    __syncthreads();
    float acc = fc_b[c];
#pragma unroll 8
    for (int k = 0; k < DH; k++) acc += srow[k] * fc_w[k * DH + c];
    float ff = fmaxf(acc, 0.0f);

    red[c] = ff * loc_w[c];
    __syncthreads();
    for (int s = 128; s > 0; s >>= 1) {
        if (c < s) red[c] += red[c + s];
        __syncthreads();
    }
    float loc = red[0] + loc_b[0];
    __syncthreads();

    red[c] = ff * scale_w[c];
    __syncthreads();
    for (int s = 128; s > 0; s >>= 1) {
        if (c < s) red[c] += red[c + s];
        __syncthreads();
    }
    if (c == 0) {
        float sraw = red[0] + scale_b[0];
        float sp = (sraw > 20.0f) ? sraw : log1pf(expf(sraw));
        float scale = sp + 1e-6f;
        float yt = y[(size_t)t * B_SZ + b];
        float z = (yt - loc) / scale;
        float lp = -0.5f * z * z - logf(scale) - 0.91893853320467274f;
        out[2 + row] = loc;
        out[2 + OUTL * B_SZ + row] = scale;
        atomicAdd(&g_loss, lp);
    }
}

__global__ void finish_k(float* __restrict__ out) {
    float L = -g_loss / (float)(OUTL * B_SZ);
    out[0] = L;
    out[1] = L;
}

// ---------------- launch -----------------------------------------------------
extern "C" void kernel_launch(void* const* d_in, const int* in_sizes, int n_in,
                              void* d_out, int out_size) {
    const float* X_cov   = (const float*)d_in[1];
    const float* X_lag   = (const float*)d_in[2];
    const float* y       = (const float*)d_in[3];
    const float* up_w    = (const float*)d_in[5];
    const float* up_b    = (const float*)d_in[6];
    const float* conv_w  = (const float*)d_in[7];
    const float* conv_b  = (const float*)d_in[8];
    const float* skip_w  = (const float*)d_in[9];
    const float* skip_b  = (const float*)d_in[10];
    const float* fc_w    = (const float*)d_in[11];
    const float* fc_b    = (const float*)d_in[12];
    const float* loc_w   = (const float*)d_in[13];
    const float* loc_b   = (const float*)d_in[14];
    const float* scale_w = (const float*)d_in[15];
    const float* scale_b = (const float*)d_in[16];
    float* out = (float*)d_out;

    cudaFuncSetAttribute(conv_mma, cudaFuncAttributeMaxDynamicSharedMemorySize, SMEM_DYN);
    cudaFuncSetAttribute(skip_mma, cudaFuncAttributeMaxDynamicSharedMemorySize, SMEM_DYN);

    const int prepTot = NL * 3 * 512 * DH;
    prep_weights<<<(prepTot + 255) / 256, 256>>>(conv_w, skip_w);
    up_kernel<<<M_TOT, 256>>>(X_lag, X_cov, up_w, up_b);
    for (int i = 0; i < NL; i++) {
        conv_mma<<<dim3(4, 512), 256, SMEM_DYN>>>(i, 1 << i, conv_b);
        skip_mma<<<dim3(4, 512), 256, SMEM_DYN>>>(i, skip_b);
    }
    final_k<<<OUTL * B_SZ, 256>>>(y, fc_w, fc_b, loc_w, loc_b, scale_w, scale_b, out);
    finish_k<<<1, 1>>>(out);
}

// round 7
// speedup vs baseline: 4.7541x; 2.0402x over previous
#include <cuda_runtime.h>
#include <cuda_bf16.h>
#include <cstdint>
#include <math.h>

#define T_LEN 1024
#define B_SZ  64
#define DH    256
#define NL    8
#define OUTL  24
#define M_TOT (B_SZ * T_LEN)

// ---------------- device scratch -------------------------------------------
__device__ __align__(128) float          g_h   [M_TOT * DH];
__device__ __align__(128) float          g_skip[M_TOT * DH];
__device__ __align__(128) __nv_bfloat16  g_hhi [M_TOT * DH];
__device__ __align__(128) __nv_bfloat16  g_hlo [M_TOT * DH];
__device__ __align__(128) __nv_bfloat16  g_ghi [M_TOT * DH];
__device__ __align__(128) __nv_bfloat16  g_glo [M_TOT * DH];
// conv weights: [layer][tap][np=512][ic=256], np = 2*c + s (s=0: f ch c, s=1: g ch c)
__device__ __align__(128) __nv_bfloat16  g_Wc_hi[NL * 3 * 512 * DH];
__device__ __align__(128) __nv_bfloat16  g_Wc_lo[NL * 3 * 512 * DH];
// skip weights: [layer][oc=512][ic=256]
__device__ __align__(128) __nv_bfloat16  g_Ws_hi[NL * 512 * DH];
__device__ __align__(128) __nv_bfloat16  g_Ws_lo[NL * 512 * DH];
__device__ float g_loss;

// ---------------- PTX helpers ------------------------------------------------
__device__ __forceinline__ uint32_t cvta_s(const void* p) {
    uint32_t a;
    asm("{ .reg .u64 t; cvta.to.shared.u64 t, %1; cvt.u32.u64 %0, t; }" : "=r"(a) : "l"(p));
    return a;
}
__device__ __forceinline__ void ldsm4(uint32_t (&r)[4], uint32_t addr) {
    asm volatile("ldmatrix.sync.aligned.m8n8.x4.shared.b16 {%0,%1,%2,%3}, [%4];"
                 : "=r"(r[0]), "=r"(r[1]), "=r"(r[2]), "=r"(r[3]) : "r"(addr));
}
__device__ __forceinline__ void mma16816(float (&c)[4], const uint32_t (&a)[4],
                                         uint32_t b0, uint32_t b1) {
    asm volatile(
        "mma.sync.aligned.m16n8k16.row.col.f32.bf16.bf16.f32 "
        "{%0,%1,%2,%3}, {%4,%5,%6,%7}, {%8,%9}, {%0,%1,%2,%3};"
        : "+f"(c[0]), "+f"(c[1]), "+f"(c[2]), "+f"(c[3])
        : "r"(a[0]), "r"(a[1]), "r"(a[2]), "r"(a[3]), "r"(b0), "r"(b1));
}
__device__ __forceinline__ void cp16(uint32_t saddr, const void* g, bool pred) {
    int sz = pred ? 16 : 0;
    asm volatile("cp.async.cg.shared.global [%0], [%1], 16, %2;"
                 :: "r"(saddr), "l"(g), "r"(sz) : "memory");
}
#define CP_COMMIT() asm volatile("cp.async.commit_group;" ::: "memory")
#define CP_WAIT1()  asm volatile("cp.async.wait_group 1;" ::: "memory")
#define CP_WAIT0()  asm volatile("cp.async.wait_group 0;" ::: "memory")

// Stage layout: superplane A @0 (128 rows x 128B = [hi 64B | lo 64B], SW128 swizzled),
//               superplane B @16KB. Stage = 32KB, 3 stages = 96KB.
#define SP_B  16384
#define STG_SZ 32768
#define SMEM_DYN (3 * STG_SZ)
#define SWA(r, c) ((uint32_t)((r) * 128 + (((c) ^ ((r) & 7)) << 4)))

// ---------------- weight pack + init -----------------------------------------
__global__ void prep_weights(const float* __restrict__ conv_w,
                             const float* __restrict__ skip_w) {
    int idx = blockIdx.x * blockDim.x + threadIdx.x;
    if (idx == 0) g_loss = 0.0f;
    const int totC = NL * 3 * 512 * DH;
    if (idx < totC) {
        int ic = idx & 255;
        int np = (idx >> 8) & 511;
        int tap = (idx >> 17) % 3;
        int layer = idx / (3 * 512 * 256);
        int c = np >> 1, s = np & 1;
        int oc = c + s * 256;
        float v = conv_w[((size_t)(layer * 512 + oc) * DH + ic) * 3 + tap];
        __nv_bfloat16 hi = __float2bfloat16(v);
        g_Wc_hi[idx] = hi;
        g_Wc_lo[idx] = __float2bfloat16(v - __bfloat162float(hi));
    }
    const int totS = NL * 512 * DH;
    if (idx < totS) {
        float v = skip_w[idx];
        __nv_bfloat16 hi = __float2bfloat16(v);
        g_Ws_hi[idx] = hi;
        g_Ws_lo[idx] = __float2bfloat16(v - __bfloat162float(hi));
    }
}

// ---------------- up projection -----------------------------------------------
__global__ __launch_bounds__(256) void up_kernel(
    const float* __restrict__ X_lag, const float* __restrict__ X_cov,
    const float* __restrict__ up_w, const float* __restrict__ up_b) {
    int r = blockIdx.x;
    int b = r / T_LEN;
    int t = r % T_LEN;
    __shared__ float x[16];
    int c = threadIdx.x;
    if (c < 8)       x[c] = X_lag[((size_t)t * B_SZ + b) * 8 + c];
    else if (c < 16) x[c] = X_cov[((size_t)t * B_SZ + b) * 8 + (c - 8)];
    __syncthreads();
    float acc = up_b[c];
#pragma unroll
    for (int j = 0; j < 16; j++) acc += x[j] * up_w[j * DH + c];
    size_t o = (size_t)r * DH + c;
    g_h[o] = acc;
    __nv_bfloat16 hi = __float2bfloat16(acc);
    g_hhi[o] = hi;
    g_hlo[o] = __float2bfloat16(acc - __bfloat162float(hi));
}

// ---------------- conv gated HMMA kernel (3-stage cp.async + SW128) -----------
// grid (4, 64*ntile): x = N-tile (128 packed = 64 ch x (f,g)), y -> (batch, t-tile)
__global__ __launch_bounds__(256, 2) void conv_mma(int layer, int dil,
                                                   int tstart, int ntile,
                                                   const float* __restrict__ conv_b) {
    extern __shared__ __align__(16) unsigned char sm[];
    const int tid = threadIdx.x, wid = tid >> 5, lid = tid & 31;
    const int wm = wid & 1, wn = wid >> 1;
    const int bidx = blockIdx.y / ntile;
    const int ttile = tstart + (blockIdx.y % ntile);
    const int n0 = blockIdx.x * 128;
    const int m0 = bidx * T_LEN + ttile * 128;
    const int t0 = ttile * 128;
    const uint32_t smb = cvta_s(sm);
    const int lrow = lid & 15, khalf = lid >> 4;
    const int lc = tid & 3, lislo = (tid >> 2) & 1, lrr = tid >> 3;

    float acc[4][4][4];
#pragma unroll
    for (int a = 0; a < 4; a++)
#pragma unroll
        for (int b = 0; b < 4; b++)
#pragma unroll
            for (int d = 0; d < 4; d++) acc[a][b][d] = 0.0f;

    const int NIT = 24;
    const int chunk = lislo * 4 + lc;
    auto issue = [&](int it) {
        int tap = it >> 3, kc = it & 7;
        int kk = kc * 32;
        int off = (2 - tap) * dil;
        const __nv_bfloat16* Asrc = (lislo ? g_hlo : g_hhi) + ((long)(m0 - off) * DH + kk) + lc * 8;
        const __nv_bfloat16* Bsrc = (lislo ? g_Wc_lo : g_Wc_hi)
                                  + ((size_t)(layer * 3 + tap) * 512 + n0) * DH + kk + lc * 8;
        uint32_t sb = smb + (it % 3) * STG_SZ;
#pragma unroll
        for (int q = 0; q < 4; q++) {
            int r = q * 32 + lrr;
            uint32_t dst = sb + SWA(r, chunk);
            cp16(dst,        Asrc + (size_t)r * DH, (t0 + r) >= off);
            cp16(dst + SP_B, Bsrc + (size_t)r * DH, true);
        }
        CP_COMMIT();
    };

    issue(0);
    issue(1);
    for (int it = 0; it < NIT; it++) {
        if (it + 1 < NIT) CP_WAIT1(); else CP_WAIT0();
        __syncthreads();
        if (it + 2 < NIT) issue(it + 2);
        uint32_t s0 = smb + (it % 3) * STG_SZ;
#pragma unroll
        for (int ks = 0; ks < 2; ks++) {
            int ch = 2 * ks + khalf;
            uint32_t a[4][4], bH[2][4], bL[2][4];
#pragma unroll
            for (int q = 0; q < 2; q++) {
                int rB = wn * 32 + q * 16 + lrow;
                ldsm4(bH[q], s0 + SP_B + SWA(rB, ch));
                ldsm4(bL[q], s0 + SP_B + SWA(rB, ch + 4));
            }
#pragma unroll
            for (int mt = 0; mt < 4; mt++) {
                int rA = wm * 64 + mt * 16 + lrow;
                ldsm4(a[mt], s0 + SWA(rA, ch));
            }
#pragma unroll
            for (int mt = 0; mt < 4; mt++)
#pragma unroll
                for (int nt = 0; nt < 4; nt++) {
                    int q = nt >> 1, h = nt & 1;
                    mma16816(acc[mt][nt], a[mt], bH[q][h], bH[q][h + 2]);
                    mma16816(acc[mt][nt], a[mt], bL[q][h], bL[q][h + 2]);
                }
#pragma unroll
            for (int mt = 0; mt < 4; mt++) {
                int rA = wm * 64 + mt * 16 + lrow;
                ldsm4(a[mt], s0 + SWA(rA, ch + 4));
            }
#pragma unroll
            for (int mt = 0; mt < 4; mt++)
#pragma unroll
                for (int nt = 0; nt < 4; nt++) {
                    int q = nt >> 1, h = nt & 1;
                    mma16816(acc[mt][nt], a[mt], bH[q][h], bH[q][h + 2]);
                }
        }
    }

    // epilogue: lane cols are (f,g) of one channel
    const float* cbf = conv_b + layer * 512;
    const int lm = lid >> 2, ln = lid & 3;
#pragma unroll
    for (int mt = 0; mt < 4; mt++) {
        int row0 = m0 + wm * 64 + mt * 16 + lm;
#pragma unroll
        for (int nt = 0; nt < 4; nt++) {
            int ch = ((n0 + wn * 32 + nt * 8) >> 1) + ln;
            float fb = __ldg(cbf + ch), gb = __ldg(cbf + 256 + ch);
#pragma unroll
            for (int u = 0; u < 2; u++) {
                int row = row0 + u * 8;
                float f = acc[mt][nt][2 * u] + fb;
                float g = acc[mt][nt][2 * u + 1] + gb;
                float e2f = __expf(2.0f * f);
                float th = (e2f - 1.0f) / (e2f + 1.0f);
                float val = th / (1.0f + __expf(-g));
                __nv_bfloat16 hi = __float2bfloat16(val);
                g_ghi[(size_t)row * DH + ch] = hi;
                g_glo[(size_t)row * DH + ch] = __float2bfloat16(val - __bfloat162float(hi));
            }
        }
    }
}

// ---------------- skip projection HMMA kernel (3-stage cp.async + SW128) -------
// grid (4, 64*ntile); skip-half N-tiles (n0>=256) only needed for t-tile 7
__global__ __launch_bounds__(256, 2) void skip_mma(int layer, int tstart, int ntile,
                                                   const float* __restrict__ skip_b) {
    const int bidx = blockIdx.y / ntile;
    const int ttile = tstart + (blockIdx.y % ntile);
    const int n0 = blockIdx.x * 128;
    if (n0 >= 256 && ttile != (T_LEN / 128 - 1)) return;  // skip-half unused below t=896
    extern __shared__ __align__(16) unsigned char sm[];
    const int tid = threadIdx.x, wid = tid >> 5, lid = tid & 31;
    const int wm = wid & 1, wn = wid >> 1;
    const int m0 = bidx * T_LEN + ttile * 128;
    const uint32_t smb = cvta_s(sm);
    const int lrow = lid & 15, khalf = lid >> 4;
    const int lc = tid & 3, lislo = (tid >> 2) & 1, lrr = tid >> 3;

    float acc[4][4][4];
#pragma unroll
    for (int a = 0; a < 4; a++)
#pragma unroll
        for (int b = 0; b < 4; b++)
#pragma unroll
            for (int d = 0; d < 4; d++) acc[a][b][d] = 0.0f;

    const __nv_bfloat16* Asrc = (lislo ? g_glo : g_ghi) + (size_t)m0 * DH + lc * 8;
    const __nv_bfloat16* Bsrc = (lislo ? g_Ws_lo : g_Ws_hi)
                              + ((size_t)layer * 512 + n0) * DH + lc * 8;
    const int chunk = lislo * 4 + lc;

    const int NIT = 8;
    auto issue = [&](int it) {
        int kk = it * 32;
        uint32_t sb = smb + (it % 3) * STG_SZ;
#pragma unroll
        for (int q = 0; q < 4; q++) {
            int r = q * 32 + lrr;
            uint32_t dst = sb + SWA(r, chunk);
            cp16(dst,        Asrc + (size_t)r * DH + kk, true);
            cp16(dst + SP_B, Bsrc + (size_t)r * DH + kk, true);
        }
        CP_COMMIT();
    };

    issue(0);
    issue(1);
    for (int it = 0; it < NIT; it++) {
        if (it + 1 < NIT) CP_WAIT1(); else CP_WAIT0();
        __syncthreads();
        if (it + 2 < NIT) issue(it + 2);
        uint32_t s0 = smb + (it % 3) * STG_SZ;
#pragma unroll
        for (int ks = 0; ks < 2; ks++) {
            int ch = 2 * ks + khalf;
            uint32_t a[4][4], bH[2][4], bL[2][4];
#pragma unroll
            for (int q = 0; q < 2; q++) {
                int rB = wn * 32 + q * 16 + lrow;
                ldsm4(bH[q], s0 + SP_B + SWA(rB, ch));
                ldsm4(bL[q], s0 + SP_B + SWA(rB, ch + 4));
            }
#pragma unroll
            for (int mt = 0; mt < 4; mt++) {
                int rA = wm * 64 + mt * 16 + lrow;
                ldsm4(a[mt], s0 + SWA(rA, ch));
            }
#pragma unroll
            for (int mt = 0; mt < 4; mt++)
#pragma unroll
                for (int nt = 0; nt < 4; nt++) {
                    int q = nt >> 1, h = nt & 1;
                    mma16816(acc[mt][nt], a[mt], bH[q][h], bH[q][h + 2]);
                    mma16816(acc[mt][nt], a[mt], bL[q][h], bL[q][h + 2]);
                }
#pragma unroll
            for (int mt = 0; mt < 4; mt++) {
                int rA = wm * 64 + mt * 16 + lrow;
                ldsm4(a[mt], s0 + SWA(rA, ch + 4));
            }
#pragma unroll
            for (int mt = 0; mt < 4; mt++)
#pragma unroll
                for (int nt = 0; nt < 4; nt++) {
                    int q = nt >> 1, h = nt & 1;
                    mma16816(acc[mt][nt], a[mt], bH[q][h], bH[q][h + 2]);
                }
        }
    }

    // epilogue
    const float* sb_ = skip_b + layer * 512;
    const int lm = lid >> 2, ln = lid & 3;
    const bool is_h = (n0 < 256);
#pragma unroll
    for (int mt = 0; mt < 4; mt++) {
        int row0 = m0 + wm * 64 + mt * 16 + lm;
#pragma unroll
        for (int nt = 0; nt < 4; nt++) {
            int oc = n0 + wn * 32 + nt * 8 + 2 * ln;
            float b0 = __ldg(sb_ + oc), b1 = __ldg(sb_ + oc + 1);
#pragma unroll
            for (int u = 0; u < 2; u++) {
                int row = row0 + u * 8;
                float v0 = acc[mt][nt][2 * u] + b0;
                float v1 = acc[mt][nt][2 * u + 1] + b1;
                if (is_h) {
                    float2* hp = (float2*)(g_h + (size_t)row * DH + oc);
                    float2 cur = *hp;
                    float nh0 = cur.x + v0, nh1 = cur.y + v1;
                    *hp = make_float2(nh0, nh1);
                    __nv_bfloat16 a0 = __float2bfloat16(nh0);
                    __nv_bfloat16 a1 = __float2bfloat16(nh1);
                    *(__nv_bfloat162*)(g_hhi + (size_t)row * DH + oc) = __nv_bfloat162(a0, a1);
                    *(__nv_bfloat162*)(g_hlo + (size_t)row * DH + oc) = __nv_bfloat162(
                        __float2bfloat16(nh0 - __bfloat162float(a0)),
                        __float2bfloat16(nh1 - __bfloat162float(a1)));
                } else {
                    float2* sp = (float2*)(g_skip + (size_t)row * DH + (oc - 256));
                    float2 prev = (layer == 0) ? make_float2(0.f, 0.f) : *sp;
                    *sp = make_float2(prev.x + v0, prev.y + v1);
                }
            }
        }
    }
}

// ---------------- FC head + Gaussian NLL ------------------------------------
__global__ __launch_bounds__(256) void final_k(
    const float* __restrict__ y,
    const float* __restrict__ fc_w, const float* __restrict__ fc_b,
    const float* __restrict__ loc_w, const float* __restrict__ loc_b,
    const float* __restrict__ scale_w, const float* __restrict__ scale_b,
    float* __restrict__ out) {
    int row = blockIdx.x;
    int tt = row >> 6;
    int b = row & 63;
    int t = T_LEN - OUTL + tt;
    size_t r = (size_t)b * T_LEN + t;
    __shared__ float srow[DH];
    __shared__ float red[256];
    int c = threadIdx.x;
    srow[c] = g_skip[r * DH + c];
    __syncthreads();
    float acc = fc_b[c];
#pragma unroll 8
    for (int k = 0; k < DH; k++) acc += srow[k] * fc_w[k * DH + c];
    float ff = fmaxf(acc, 0.0f);

    red[c] = ff * loc_w[c];
    __syncthreads();
    for (int s = 128; s > 0; s >>= 1) {
        if (c < s) red[c] += red[c + s];
        __syncthreads();
    }
    float loc = red[0] + loc_b[0];
    __syncthreads();

    red[c] = ff * scale_w[c];
    __syncthreads();
    for (int s = 128; s > 0; s >>= 1) {
        if (c < s) red[c] += red[c + s];
        __syncthreads();
    }
    if (c == 0) {
        float sraw = red[0] + scale_b[0];
        float sp = (sraw > 20.0f) ? sraw : log1pf(expf(sraw));
        float scale = sp + 1e-6f;
        float yt = y[(size_t)t * B_SZ + b];
        float z = (yt - loc) / scale;
        float lp = -0.5f * z * z - logf(scale) - 0.91893853320467274f;
        out[2 + row] = loc;
        out[2 + OUTL * B_SZ + row] = scale;
        atomicAdd(&g_loss, lp);
    }
}

__global__ void finish_k(float* __restrict__ out) {
    float L = -g_loss / (float)(OUTL * B_SZ);
    out[0] = L;
    out[1] = L;
}

// ---------------- launch -----------------------------------------------------
extern "C" void kernel_launch(void* const* d_in, const int* in_sizes, int n_in,
                              void* d_out, int out_size) {
    const float* X_cov   = (const float*)d_in[1];
    const float* X_lag   = (const float*)d_in[2];
    const float* y       = (const float*)d_in[3];
    const float* up_w    = (const float*)d_in[5];
    const float* up_b    = (const float*)d_in[6];
    const float* conv_w  = (const float*)d_in[7];
    const float* conv_b  = (const float*)d_in[8];
    const float* skip_w  = (const float*)d_in[9];
    const float* skip_b  = (const float*)d_in[10];
    const float* fc_w    = (const float*)d_in[11];
    const float* fc_b    = (const float*)d_in[12];
    const float* loc_w   = (const float*)d_in[13];
    const float* loc_b   = (const float*)d_in[14];
    const float* scale_w = (const float*)d_in[15];
    const float* scale_b = (const float*)d_in[16];
    float* out = (float*)d_out;

    cudaFuncSetAttribute(conv_mma, cudaFuncAttributeMaxDynamicSharedMemorySize, SMEM_DYN);
    cudaFuncSetAttribute(skip_mma, cudaFuncAttributeMaxDynamicSharedMemorySize, SMEM_DYN);

    // Needed-row thresholds: thr_i = 488 + 2^(i+2); t-tile start = thr_i / 128.
    static const int TSTART[NL] = {3, 3, 3, 4, 4, 4, 5, 7};

    const int prepTot = NL * 3 * 512 * DH;
    prep_weights<<<(prepTot + 255) / 256, 256>>>(conv_w, skip_w);
    up_kernel<<<M_TOT, 256>>>(X_lag, X_cov, up_w, up_b);
    for (int i = 0; i < NL; i++) {
        int ts = TSTART[i];
        int nt = (T_LEN / 128) - ts;
        conv_mma<<<dim3(4, 64 * nt), 256, SMEM_DYN>>>(i, 1 << i, ts, nt, conv_b);
        skip_mma<<<dim3(4, 64 * nt), 256, SMEM_DYN>>>(i, ts, nt, skip_b);
    }
    final_k<<<OUTL * B_SZ, 256>>>(y, fc_w, fc_b, loc_w, loc_b, scale_w, scale_b, out);
    finish_k<<<1, 1>>>(out);
}

// round 8
// speedup vs baseline: 4.9741x; 1.0463x over previous
#include <cuda_runtime.h>
#include <cuda_bf16.h>
#include <cstdint>
#include <math.h>

#define T_LEN 1024
#define B_SZ  64
#define DH    256
#define NL    8
#define OUTL  24
#define M_TOT (B_SZ * T_LEN)
#define UP_T0 376                 // first timestep whose h is ever read

// ---------------- device scratch -------------------------------------------
__device__ __align__(128) float          g_h   [M_TOT * DH];
__device__ __align__(128) float          g_skip[M_TOT * DH];
__device__ __align__(128) __nv_bfloat16  g_hhi [M_TOT * DH];
__device__ __align__(128) __nv_bfloat16  g_hlo [M_TOT * DH];
__device__ __align__(128) __nv_bfloat16  g_ghi [M_TOT * DH];
__device__ __align__(128) __nv_bfloat16  g_glo [M_TOT * DH];
// conv weights: [layer][tap][np=512][ic=256], np = 2*c + s (s=0: f ch c, s=1: g ch c)
__device__ __align__(128) __nv_bfloat16  g_Wc_hi[NL * 3 * 512 * DH];
__device__ __align__(128) __nv_bfloat16  g_Wc_lo[NL * 3 * 512 * DH];
// skip weights: [layer][oc=512][ic=256]
__device__ __align__(128) __nv_bfloat16  g_Ws_hi[NL * 512 * DH];
__device__ __align__(128) __nv_bfloat16  g_Ws_lo[NL * 512 * DH];
__device__ float g_loss;

// ---------------- PTX helpers ------------------------------------------------
__device__ __forceinline__ uint32_t cvta_s(const void* p) {
    uint32_t a;
    asm("{ .reg .u64 t; cvta.to.shared.u64 t, %1; cvt.u32.u64 %0, t; }" : "=r"(a) : "l"(p));
    return a;
}
__device__ __forceinline__ void ldsm4(uint32_t (&r)[4], uint32_t addr) {
    asm volatile("ldmatrix.sync.aligned.m8n8.x4.shared.b16 {%0,%1,%2,%3}, [%4];"
                 : "=r"(r[0]), "=r"(r[1]), "=r"(r[2]), "=r"(r[3]) : "r"(addr));
}
__device__ __forceinline__ void mma16816(float (&c)[4], const uint32_t (&a)[4],
                                         uint32_t b0, uint32_t b1) {
    asm volatile(
        "mma.sync.aligned.m16n8k16.row.col.f32.bf16.bf16.f32 "
        "{%0,%1,%2,%3}, {%4,%5,%6,%7}, {%8,%9}, {%0,%1,%2,%3};"
        : "+f"(c[0]), "+f"(c[1]), "+f"(c[2]), "+f"(c[3])
        : "r"(a[0]), "r"(a[1]), "r"(a[2]), "r"(a[3]), "r"(b0), "r"(b1));
}
__device__ __forceinline__ void cp16(uint32_t saddr, const void* g, bool pred) {
    int sz = pred ? 16 : 0;
    asm volatile("cp.async.cg.shared.global [%0], [%1], 16, %2;"
                 :: "r"(saddr), "l"(g), "r"(sz) : "memory");
}
#define CP_COMMIT() asm volatile("cp.async.commit_group;" ::: "memory")
#define CP_WAIT1()  asm volatile("cp.async.wait_group 1;" ::: "memory")
#define CP_WAIT0()  asm volatile("cp.async.wait_group 0;" ::: "memory")

// Stage: superplane A @0 (128 rows x 128B = [hi 64B | lo 64B], swizzled), B @16KB.
#define SP_B  16384
#define STG_SZ 32768
#define SMEM_DYN (3 * STG_SZ)
#define SWA(r, c) ((uint32_t)((r) * 128 + (((c) ^ ((r) & 7)) << 4)))

// ---------------- weight pack + init -----------------------------------------
__global__ void prep_weights(const float* __restrict__ conv_w,
                             const float* __restrict__ skip_w) {
    int idx = blockIdx.x * blockDim.x + threadIdx.x;
    if (idx == 0) g_loss = 0.0f;
    const int totC = NL * 3 * 512 * DH;
    if (idx < totC) {
        int ic = idx & 255;
        int np = (idx >> 8) & 511;
        int tap = (idx >> 17) % 3;
        int layer = idx / (3 * 512 * 256);
        int c = np >> 1, s = np & 1;
        int oc = c + s * 256;
        float v = conv_w[((size_t)(layer * 512 + oc) * DH + ic) * 3 + tap];
        __nv_bfloat16 hi = __float2bfloat16(v);
        g_Wc_hi[idx] = hi;
        g_Wc_lo[idx] = __float2bfloat16(v - __bfloat162float(hi));
    }
    const int totS = NL * 512 * DH;
    if (idx < totS) {
        float v = skip_w[idx];
        __nv_bfloat16 hi = __float2bfloat16(v);
        g_Ws_hi[idx] = hi;
        g_Ws_lo[idx] = __float2bfloat16(v - __bfloat162float(hi));
    }
}

// ---------------- up projection (only t >= UP_T0 is ever consumed) -----------
__global__ __launch_bounds__(256) void up_kernel(
    const float* __restrict__ X_lag, const float* __restrict__ X_cov,
    const float* __restrict__ up_w, const float* __restrict__ up_b) {
    const int span = T_LEN - UP_T0;
    int blk = blockIdx.x;
    int b = blk / span;
    int t = UP_T0 + blk % span;
    int r = b * T_LEN + t;
    __shared__ float x[16];
    int c = threadIdx.x;
    if (c < 8)       x[c] = X_lag[((size_t)t * B_SZ + b) * 8 + c];
    else if (c < 16) x[c] = X_cov[((size_t)t * B_SZ + b) * 8 + (c - 8)];
    __syncthreads();
    float acc = up_b[c];
#pragma unroll
    for (int j = 0; j < 16; j++) acc += x[j] * up_w[j * DH + c];
    size_t o = (size_t)r * DH + c;
    g_h[o] = acc;
    __nv_bfloat16 hi = __float2bfloat16(acc);
    g_hhi[o] = hi;
    g_hlo[o] = __float2bfloat16(acc - __bfloat162float(hi));
}

// ---------------- conv gated HMMA kernel (unrolled 3-stage pipeline) ----------
__global__ __launch_bounds__(256, 2) void conv_mma(int layer, int dil,
                                                   int tstart, int ntile,
                                                   const float* __restrict__ conv_b) {
    extern __shared__ __align__(16) unsigned char sm[];
    const int tid = threadIdx.x, wid = tid >> 5, lid = tid & 31;
    const int wm = wid & 1, wn = wid >> 1;
    const int bidx = blockIdx.y / ntile;
    const int ttile = tstart + (blockIdx.y % ntile);
    const int n0 = blockIdx.x * 128;
    const int m0 = bidx * T_LEN + ttile * 128;
    const int t0 = ttile * 128;
    const uint32_t smb = cvta_s(sm);
    const int lrow = lid & 15, khalf = lid >> 4;
    const int lc = tid & 3, lislo = (tid >> 2) & 1, lrr = tid >> 3;

    float acc[4][4][4];
#pragma unroll
    for (int a = 0; a < 4; a++)
#pragma unroll
        for (int b = 0; b < 4; b++)
#pragma unroll
            for (int d = 0; d < 4; d++) acc[a][b][d] = 0.0f;

    const int chunk = lislo * 4 + lc;
    auto issue = [&](int it, uint32_t stgoff) {
        int tap = it >> 3, kc = it & 7;
        int kk = kc * 32;
        int off = (2 - tap) * dil;
        const __nv_bfloat16* Asrc = (lislo ? g_hlo : g_hhi) + ((long)(m0 - off) * DH + kk) + lc * 8;
        const __nv_bfloat16* Bsrc = (lislo ? g_Wc_lo : g_Wc_hi)
                                  + ((size_t)(layer * 3 + tap) * 512 + n0) * DH + kk + lc * 8;
        uint32_t sb = smb + stgoff;
#pragma unroll
        for (int q = 0; q < 4; q++) {
            int r = q * 32 + lrr;
            uint32_t dst = sb + SWA(r, chunk);
            cp16(dst,        Asrc + (size_t)r * DH, (t0 + r) >= off);
            cp16(dst + SP_B, Bsrc + (size_t)r * DH, true);
        }
        CP_COMMIT();
    };

    auto compute = [&](uint32_t s0) {
#pragma unroll
        for (int ks = 0; ks < 2; ks++) {
            int ch = 2 * ks + khalf;
            uint32_t a[4][4], bH[2][4], bL[2][4];
#pragma unroll
            for (int q = 0; q < 2; q++) {
                int rB = wn * 32 + q * 16 + lrow;
                ldsm4(bH[q], s0 + SP_B + SWA(rB, ch));
                ldsm4(bL[q], s0 + SP_B + SWA(rB, ch + 4));
            }
#pragma unroll
            for (int mt = 0; mt < 4; mt++) {
                int rA = wm * 64 + mt * 16 + lrow;
                ldsm4(a[mt], s0 + SWA(rA, ch));
            }
#pragma unroll
            for (int mt = 0; mt < 4; mt++)
#pragma unroll
                for (int nt = 0; nt < 4; nt++) {
                    int q = nt >> 1, h = nt & 1;
                    mma16816(acc[mt][nt], a[mt], bH[q][h], bH[q][h + 2]);
                    mma16816(acc[mt][nt], a[mt], bL[q][h], bL[q][h + 2]);
                }
#pragma unroll
            for (int mt = 0; mt < 4; mt++) {
                int rA = wm * 64 + mt * 16 + lrow;
                ldsm4(a[mt], s0 + SWA(rA, ch + 4));
            }
#pragma unroll
            for (int mt = 0; mt < 4; mt++)
#pragma unroll
                for (int nt = 0; nt < 4; nt++) {
                    int q = nt >> 1, h = nt & 1;
                    mma16816(acc[mt][nt], a[mt], bH[q][h], bH[q][h + 2]);
                }
        }
    };

    issue(0, 0);
    issue(1, STG_SZ);
    for (int mj = 0; mj < 7; mj++) {
        int b0 = mj * 3;
        CP_WAIT1(); __syncthreads(); issue(b0 + 2, 2 * STG_SZ); compute(smb);
        CP_WAIT1(); __syncthreads(); issue(b0 + 3, 0);          compute(smb + STG_SZ);
        CP_WAIT1(); __syncthreads(); issue(b0 + 4, STG_SZ);     compute(smb + 2 * STG_SZ);
    }
    CP_WAIT1(); __syncthreads(); issue(23, 2 * STG_SZ); compute(smb);              // it=21
    CP_WAIT1(); __syncthreads();                         compute(smb + STG_SZ);     // it=22
    CP_WAIT0(); __syncthreads();                         compute(smb + 2 * STG_SZ); // it=23

    // epilogue: lane cols are (f,g) of one channel
    const float* cbf = conv_b + layer * 512;
    const int lm = lid >> 2, ln = lid & 3;
#pragma unroll
    for (int mt = 0; mt < 4; mt++) {
        int row0 = m0 + wm * 64 + mt * 16 + lm;
#pragma unroll
        for (int nt = 0; nt < 4; nt++) {
            int ch = ((n0 + wn * 32 + nt * 8) >> 1) + ln;
            float fb = __ldg(cbf + ch), gb = __ldg(cbf + 256 + ch);
#pragma unroll
            for (int u = 0; u < 2; u++) {
                int row = row0 + u * 8;
                float f = acc[mt][nt][2 * u] + fb;
                float g = acc[mt][nt][2 * u + 1] + gb;
                float e2f = __expf(2.0f * f);
                float th = (e2f - 1.0f) / (e2f + 1.0f);
                float val = th / (1.0f + __expf(-g));
                __nv_bfloat16 hi = __float2bfloat16(val);
                g_ghi[(size_t)row * DH + ch] = hi;
                g_glo[(size_t)row * DH + ch] = __float2bfloat16(val - __bfloat162float(hi));
            }
        }
    }
}

// ---------------- skip projection HMMA kernel (packed grid, unrolled) ---------
// grid (2, 64*(ntile+1)): j<ntile -> h-half tile; j==ntile -> skip-half @ ttile=7
__global__ __launch_bounds__(256, 2) void skip_mma(int layer, int tstart, int ntile,
                                                   const float* __restrict__ skip_b) {
    extern __shared__ __align__(16) unsigned char sm[];
    const int per = ntile + 1;
    const int bidx = blockIdx.y / per;
    const int j = blockIdx.y % per;
    const int ttile = (j < ntile) ? (tstart + j) : (T_LEN / 128 - 1);
    const int n0 = ((j < ntile) ? 0 : 256) + blockIdx.x * 128;
    const int m0 = bidx * T_LEN + ttile * 128;

    const int tid = threadIdx.x, wid = tid >> 5, lid = tid & 31;
    const int wm = wid & 1, wn = wid >> 1;
    const uint32_t smb = cvta_s(sm);
    const int lrow = lid & 15, khalf = lid >> 4;
    const int lc = tid & 3, lislo = (tid >> 2) & 1, lrr = tid >> 3;

    float acc[4][4][4];
#pragma unroll
    for (int a = 0; a < 4; a++)
#pragma unroll
        for (int b = 0; b < 4; b++)
#pragma unroll
            for (int d = 0; d < 4; d++) acc[a][b][d] = 0.0f;

    const __nv_bfloat16* Asrc = (lislo ? g_glo : g_ghi) + (size_t)m0 * DH + lc * 8;
    const __nv_bfloat16* Bsrc = (lislo ? g_Ws_lo : g_Ws_hi)
                              + ((size_t)layer * 512 + n0) * DH + lc * 8;
    const int chunk = lislo * 4 + lc;

    auto issue = [&](int it, uint32_t stgoff) {
        int kk = it * 32;
        uint32_t sb = smb + stgoff;
#pragma unroll
        for (int q = 0; q < 4; q++) {
            int r = q * 32 + lrr;
            uint32_t dst = sb + SWA(r, chunk);
            cp16(dst,        Asrc + (size_t)r * DH + kk, true);
            cp16(dst + SP_B, Bsrc + (size_t)r * DH + kk, true);
        }
        CP_COMMIT();
    };

    auto compute = [&](uint32_t s0) {
#pragma unroll
        for (int ks = 0; ks < 2; ks++) {
            int ch = 2 * ks + khalf;
            uint32_t a[4][4], bH[2][4], bL[2][4];
#pragma unroll
            for (int q = 0; q < 2; q++) {
                int rB = wn * 32 + q * 16 + lrow;
                ldsm4(bH[q], s0 + SP_B + SWA(rB, ch));
                ldsm4(bL[q], s0 + SP_B + SWA(rB, ch + 4));
            }
#pragma unroll
            for (int mt = 0; mt < 4; mt++) {
                int rA = wm * 64 + mt * 16 + lrow;
                ldsm4(a[mt], s0 + SWA(rA, ch));
            }
#pragma unroll
            for (int mt = 0; mt < 4; mt++)
#pragma unroll
                for (int nt = 0; nt < 4; nt++) {
                    int q = nt >> 1, h = nt & 1;
                    mma16816(acc[mt][nt], a[mt], bH[q][h], bH[q][h + 2]);
                    mma16816(acc[mt][nt], a[mt], bL[q][h], bL[q][h + 2]);
                }
#pragma unroll
            for (int mt = 0; mt < 4; mt++) {
                int rA = wm * 64 + mt * 16 + lrow;
                ldsm4(a[mt], s0 + SWA(rA, ch + 4));
            }
#pragma unroll
            for (int mt = 0; mt < 4; mt++)
#pragma unroll
                for (int nt = 0; nt < 4; nt++) {
                    int q = nt >> 1, h = nt & 1;
                    mma16816(acc[mt][nt], a[mt], bH[q][h], bH[q][h + 2]);
                }
        }
    };

    issue(0, 0);
    issue(1, STG_SZ);
    CP_WAIT1(); __syncthreads(); issue(2, 2 * STG_SZ); compute(smb);
    CP_WAIT1(); __syncthreads(); issue(3, 0);          compute(smb + STG_SZ);
    CP_WAIT1(); __syncthreads(); issue(4, STG_SZ);     compute(smb + 2 * STG_SZ);
    CP_WAIT1(); __syncthreads(); issue(5, 2 * STG_SZ); compute(smb);
    CP_WAIT1(); __syncthreads(); issue(6, 0);          compute(smb + STG_SZ);
    CP_WAIT1(); __syncthreads(); issue(7, STG_SZ);     compute(smb + 2 * STG_SZ);
    CP_WAIT1(); __syncthreads();                       compute(smb);
    CP_WAIT0(); __syncthreads();                       compute(smb + STG_SZ);

    // epilogue
    const float* sb_ = skip_b + layer * 512;
    const int lm = lid >> 2, ln = lid & 3;
    const bool is_h = (n0 < 256);
#pragma unroll
    for (int mt = 0; mt < 4; mt++) {
        int row0 = m0 + wm * 64 + mt * 16 + lm;
#pragma unroll
        for (int nt = 0; nt < 4; nt++) {
            int oc = n0 + wn * 32 + nt * 8 + 2 * ln;
            float b0 = __ldg(sb_ + oc), b1 = __ldg(sb_ + oc + 1);
#pragma unroll
            for (int u = 0; u < 2; u++) {
                int row = row0 + u * 8;
                float v0 = acc[mt][nt][2 * u] + b0;
                float v1 = acc[mt][nt][2 * u + 1] + b1;
                if (is_h) {
                    float2* hp = (float2*)(g_h + (size_t)row * DH + oc);
                    float2 cur = *hp;
                    float nh0 = cur.x + v0, nh1 = cur.y + v1;
                    *hp = make_float2(nh0, nh1);
                    __nv_bfloat16 a0 = __float2bfloat16(nh0);
                    __nv_bfloat16 a1 = __float2bfloat16(nh1);
                    *(__nv_bfloat162*)(g_hhi + (size_t)row * DH + oc) = __nv_bfloat162(a0, a1);
                    *(__nv_bfloat162*)(g_hlo + (size_t)row * DH + oc) = __nv_bfloat162(
                        __float2bfloat16(nh0 - __bfloat162float(a0)),
                        __float2bfloat16(nh1 - __bfloat162float(a1)));
                } else {
                    float2* sp = (float2*)(g_skip + (size_t)row * DH + (oc - 256));
                    float2 prev = (layer == 0) ? make_float2(0.f, 0.f) : *sp;
                    *sp = make_float2(prev.x + v0, prev.y + v1);
                }
            }
        }
    }
}

// ---------------- FC head + Gaussian NLL ------------------------------------
__global__ __launch_bounds__(256) void final_k(
    const float* __restrict__ y,
    const float* __restrict__ fc_w, const float* __restrict__ fc_b,
    const float* __restrict__ loc_w, const float* __restrict__ loc_b,
    const float* __restrict__ scale_w, const float* __restrict__ scale_b,
    float* __restrict__ out) {
    int row = blockIdx.x;
    int tt = row >> 6;
    int b = row & 63;
    int t = T_LEN - OUTL + tt;
    size_t r = (size_t)b * T_LEN + t;
    __shared__ float srow[DH];
    __shared__ float red[256];
    int c = threadIdx.x;
    srow[c] = g_skip[r * DH + c];
    __syncthreads();
    float acc = fc_b[c];
#pragma unroll 8
    for (int k = 0; k < DH; k++) acc += srow[k] * fc_w[k * DH + c];
    float ff = fmaxf(acc, 0.0f);

    red[c] = ff * loc_w[c];
    __syncthreads();
    for (int s = 128; s > 0; s >>= 1) {
        if (c < s) red[c] += red[c + s];
        __syncthreads();
    }
    float loc = red[0] + loc_b[0];
    __syncthreads();

    red[c] = ff * scale_w[c];
    __syncthreads();
    for (int s = 128; s > 0; s >>= 1) {
        if (c < s) red[c] += red[c + s];
        __syncthreads();
    }
    if (c == 0) {
        float sraw = red[0] + scale_b[0];
        float sp = (sraw > 20.0f) ? sraw : log1pf(expf(sraw));
        float scale = sp + 1e-6f;
        float yt = y[(size_t)t * B_SZ + b];
        float z = (yt - loc) / scale;
        float lp = -0.5f * z * z - logf(scale) - 0.91893853320467274f;
        out[2 + row] = loc;
        out[2 + OUTL * B_SZ + row] = scale;
        atomicAdd(&g_loss, lp);
    }
}

__global__ void finish_k(float* __restrict__ out) {
    float L = -g_loss / (float)(OUTL * B_SZ);
    out[0] = L;
    out[1] = L;
}

// ---------------- launch -----------------------------------------------------
extern "C" void kernel_launch(void* const* d_in, const int* in_sizes, int n_in,
                              void* d_out, int out_size) {
    const float* X_cov   = (const float*)d_in[1];
    const float* X_lag   = (const float*)d_in[2];
    const float* y       = (const float*)d_in[3];
    const float* up_w    = (const float*)d_in[5];
    const float* up_b    = (const float*)d_in[6];
    const float* conv_w  = (const float*)d_in[7];
    const float* conv_b  = (const float*)d_in[8];
    const float* skip_w  = (const float*)d_in[9];
    const float* skip_b  = (const float*)d_in[10];
    const float* fc_w    = (const float*)d_in[11];
    const float* fc_b    = (const float*)d_in[12];
    const float* loc_w   = (const float*)d_in[13];
    const float* loc_b   = (const float*)d_in[14];
    const float* scale_w = (const float*)d_in[15];
    const float* scale_b = (const float*)d_in[16];
    float* out = (float*)d_out;

    cudaFuncSetAttribute(conv_mma, cudaFuncAttributeMaxDynamicSharedMemorySize, SMEM_DYN);
    cudaFuncSetAttribute(skip_mma, cudaFuncAttributeMaxDynamicSharedMemorySize, SMEM_DYN);

    // Needed-row thresholds: thr_i = 488 + 2^(i+2); t-tile start = thr_i / 128.
    static const int TSTART[NL] = {3, 3, 3, 4, 4, 4, 5, 7};

    const int prepTot = NL * 3 * 512 * DH;
    prep_weights<<<(prepTot + 255) / 256, 256>>>(conv_w, skip_w);
    up_kernel<<<B_SZ * (T_LEN - UP_T0), 256>>>(X_lag, X_cov, up_w, up_b);
    for (int i = 0; i < NL; i++) {
        int ts = TSTART[i];
        int nt = (T_LEN / 128) - ts;
        conv_mma<<<dim3(4, 64 * nt), 256, SMEM_DYN>>>(i, 1 << i, ts, nt, conv_b);
        skip_mma<<<dim3(2, 64 * (nt + 1)), 256, SMEM_DYN>>>(i, ts, nt, skip_b);
    }
    final_k<<<OUTL * B_SZ, 256>>>(y, fc_w, fc_b, loc_w, loc_b, scale_w, scale_b, out);
    finish_k<<<1, 1>>>(out);
}

// round 9
// speedup vs baseline: 5.5692x; 1.1196x over previous
#include <cuda_runtime.h>
#include <cuda_bf16.h>
#include <cstdint>
#include <math.h>

#define T_LEN 1024
#define B_SZ  64
#define DH    256
#define NL    8
#define OUTL  24
#define M_TOT (B_SZ * T_LEN)
#define UP_T0 376                 // first timestep whose h is ever read

// ---------------- device scratch -------------------------------------------
__device__ __align__(128) float          g_h   [M_TOT * DH];
__device__ __align__(128) float          g_skip[M_TOT * DH];
__device__ __align__(128) __nv_bfloat16  g_hhi [M_TOT * DH];
__device__ __align__(128) __nv_bfloat16  g_hlo [M_TOT * DH];
__device__ __align__(128) __nv_bfloat16  g_ghi [M_TOT * DH];
__device__ __align__(128) __nv_bfloat16  g_glo [M_TOT * DH];
__device__ __align__(128) __nv_bfloat16  g_Wc_hi[NL * 3 * 512 * DH];
__device__ __align__(128) __nv_bfloat16  g_Wc_lo[NL * 3 * 512 * DH];
__device__ __align__(128) __nv_bfloat16  g_Ws_hi[NL * 512 * DH];
__device__ __align__(128) __nv_bfloat16  g_Ws_lo[NL * 512 * DH];
__device__ float g_loss;
// dependency flags: per (layer, batch, t-tile)
__device__ int g_cdone[NL * B_SZ * 8];
__device__ int g_sdone[NL * B_SZ * 8];

// layer schedule: t-tile start per layer, and per-layer block counts
__constant__ int c_ts[NL]    = {3, 3, 3, 4, 4, 4, 5, 7};
__constant__ int c_convn[NL] = {1280, 1280, 1280, 1024, 1024, 1024, 768, 256}; // 256*nt
__constant__ int c_skipn[NL] = {768, 768, 768, 640, 640, 640, 512, 256};       // 128*(nt+1)
#define MEGA_BLOCKS 12928

// ---------------- PTX helpers ------------------------------------------------
__device__ __forceinline__ uint32_t cvta_s(const void* p) {
    uint32_t a;
    asm("{ .reg .u64 t; cvta.to.shared.u64 t, %1; cvt.u32.u64 %0, t; }" : "=r"(a) : "l"(p));
    return a;
}
__device__ __forceinline__ void ldsm4(uint32_t (&r)[4], uint32_t addr) {
    asm volatile("ldmatrix.sync.aligned.m8n8.x4.shared.b16 {%0,%1,%2,%3}, [%4];"
                 : "=r"(r[0]), "=r"(r[1]), "=r"(r[2]), "=r"(r[3]) : "r"(addr));
}
__device__ __forceinline__ void mma16816(float (&c)[4], const uint32_t (&a)[4],
                                         uint32_t b0, uint32_t b1) {
    asm volatile(
        "mma.sync.aligned.m16n8k16.row.col.f32.bf16.bf16.f32 "
        "{%0,%1,%2,%3}, {%4,%5,%6,%7}, {%8,%9}, {%0,%1,%2,%3};"
        : "+f"(c[0]), "+f"(c[1]), "+f"(c[2]), "+f"(c[3])
        : "r"(a[0]), "r"(a[1]), "r"(a[2]), "r"(a[3]), "r"(b0), "r"(b1));
}
__device__ __forceinline__ void cp16(uint32_t saddr, const void* g, bool pred) {
    int sz = pred ? 16 : 0;
    asm volatile("cp.async.cg.shared.global [%0], [%1], 16, %2;"
                 :: "r"(saddr), "l"(g), "r"(sz) : "memory");
}
#define CP_COMMIT() asm volatile("cp.async.commit_group;" ::: "memory")
#define CP_WAIT1()  asm volatile("cp.async.wait_group 1;" ::: "memory")
#define CP_WAIT0()  asm volatile("cp.async.wait_group 0;" ::: "memory")

__device__ __forceinline__ int ld_acq(const int* p) {
    int v;
    asm volatile("ld.acquire.gpu.global.b32 %0, [%1];" : "=r"(v) : "l"(p) : "memory");
    return v;
}
__device__ __forceinline__ void red_rel_add(int* p) {
    asm volatile("red.release.gpu.global.add.s32 [%0], 1;" :: "l"(p) : "memory");
}

// Stage: superplane A @0 (128 rows x 128B = [hi 64B | lo 64B], swizzled), B @16KB.
#define SP_B  16384
#define STG_SZ 32768
#define SMEM_DYN (3 * STG_SZ)
#define SWA(r, c) ((uint32_t)((r) * 128 + (((c) ^ ((r) & 7)) << 4)))

// ---------------- weight pack + flag zero -------------------------------------
__global__ void prep_weights(const float* __restrict__ conv_w,
                             const float* __restrict__ skip_w) {
    int idx = blockIdx.x * blockDim.x + threadIdx.x;
    if (idx == 0) g_loss = 0.0f;
    if (idx < NL * B_SZ * 8) { g_cdone[idx] = 0; g_sdone[idx] = 0; }
    const int totC = NL * 3 * 512 * DH;
    if (idx < totC) {
        int ic = idx & 255;
        int np = (idx >> 8) & 511;
        int tap = (idx >> 17) % 3;
        int layer = idx / (3 * 512 * 256);
        int c = np >> 1, s = np & 1;
        int oc = c + s * 256;
        float v = conv_w[((size_t)(layer * 512 + oc) * DH + ic) * 3 + tap];
        __nv_bfloat16 hi = __float2bfloat16(v);
        g_Wc_hi[idx] = hi;
        g_Wc_lo[idx] = __float2bfloat16(v - __bfloat162float(hi));
    }
    const int totS = NL * 512 * DH;
    if (idx < totS) {
        float v = skip_w[idx];
        __nv_bfloat16 hi = __float2bfloat16(v);
        g_Ws_hi[idx] = hi;
        g_Ws_lo[idx] = __float2bfloat16(v - __bfloat162float(hi));
    }
}

// ---------------- up projection (only t >= UP_T0 is ever consumed) -----------
__global__ __launch_bounds__(256) void up_kernel(
    const float* __restrict__ X_lag, const float* __restrict__ X_cov,
    const float* __restrict__ up_w, const float* __restrict__ up_b) {
    const int span = T_LEN - UP_T0;
    int blk = blockIdx.x;
    int b = blk / span;
    int t = UP_T0 + blk % span;
    int r = b * T_LEN + t;
    __shared__ float x[16];
    int c = threadIdx.x;
    if (c < 8)       x[c] = X_lag[((size_t)t * B_SZ + b) * 8 + c];
    else if (c < 16) x[c] = X_cov[((size_t)t * B_SZ + b) * 8 + (c - 8)];
    __syncthreads();
    float acc = up_b[c];
#pragma unroll
    for (int j = 0; j < 16; j++) acc += x[j] * up_w[j * DH + c];
    size_t o = (size_t)r * DH + c;
    g_h[o] = acc;
    __nv_bfloat16 hi = __float2bfloat16(acc);
    g_hhi[o] = hi;
    g_hlo[o] = __float2bfloat16(acc - __bfloat162float(hi));
}

// ---------------- mega kernel: all 8 layers (conv + skip) with spin deps ------
__global__ __launch_bounds__(256, 2) void mega(const float* __restrict__ conv_b,
                                               const float* __restrict__ skip_b) {
    extern __shared__ __align__(16) unsigned char sm[];
    // ---- decode (layer, role, tile) from linear block id ----
    int rem = blockIdx.x;
    int layer = 0;
    while (layer < NL - 1 && rem >= c_convn[layer] + c_skipn[layer]) {
        rem -= c_convn[layer] + c_skipn[layer];
        layer++;
    }
    const int tstart = c_ts[layer];
    const int nt = 8 - tstart;
    const bool isconv = rem < c_convn[layer];

    const int tid = threadIdx.x, wid = tid >> 5, lid = tid & 31;
    const int wm = wid & 1, wn = wid >> 1;
    const uint32_t smb = cvta_s(sm);
    const int lrow = lid & 15, khalf = lid >> 4;
    const int lc = tid & 3, lislo = (tid >> 2) & 1, lrr = tid >> 3;
    const int chunk = lislo * 4 + lc;

    float acc[4][4][4];
#pragma unroll
    for (int a = 0; a < 4; a++)
#pragma unroll
        for (int b = 0; b < 4; b++)
#pragma unroll
            for (int d = 0; d < 4; d++) acc[a][b][d] = 0.0f;

    if (isconv) {
        const int nx = rem & 3;
        const int y = rem >> 2;
        const int bidx = y / nt;
        const int ttile = tstart + y % nt;
        const int n0 = nx * 128;
        const int m0 = bidx * T_LEN + ttile * 128;
        const int t0 = ttile * 128;
        const int dil = 1 << layer;

        // wait on skip of layer-1 for tiles [max(ttile-2, ts_prev) .. ttile]
        if (layer > 0 && tid == 0) {
            int lo = ttile - 2, tsp = c_ts[layer - 1];
            if (lo < tsp) lo = tsp;
            for (int tp = lo; tp <= ttile; tp++) {
                int tgt = (tp == 7) ? 4 : 2;
                int* f = &g_sdone[((layer - 1) * B_SZ + bidx) * 8 + tp];
                while (ld_acq(f) < tgt) __nanosleep(64);
            }
        }
        __syncthreads();

        auto issue = [&](int it, uint32_t stgoff) {
            int tap = it >> 3, kc = it & 7;
            int kk = kc * 32;
            int off = (2 - tap) * dil;
            const __nv_bfloat16* Asrc = (lislo ? g_hlo : g_hhi)
                                      + ((long)(m0 - off) * DH + kk) + lc * 8;
            const __nv_bfloat16* Bsrc = (lislo ? g_Wc_lo : g_Wc_hi)
                                      + ((size_t)(layer * 3 + tap) * 512 + n0) * DH + kk + lc * 8;
            uint32_t sb = smb + stgoff;
#pragma unroll
            for (int q = 0; q < 4; q++) {
                int r = q * 32 + lrr;
                uint32_t dst = sb + SWA(r, chunk);
                cp16(dst,        Asrc + (size_t)r * DH, (t0 + r) >= off);
                cp16(dst + SP_B, Bsrc + (size_t)r * DH, true);
            }
            CP_COMMIT();
        };
        auto compute = [&](uint32_t s0) {
#pragma unroll
            for (int ks = 0; ks < 2; ks++) {
                int ch = 2 * ks + khalf;
                uint32_t a[4][4], bH[2][4], bL[2][4];
#pragma unroll
                for (int q = 0; q < 2; q++) {
                    int rB = wn * 32 + q * 16 + lrow;
                    ldsm4(bH[q], s0 + SP_B + SWA(rB, ch));
                    ldsm4(bL[q], s0 + SP_B + SWA(rB, ch + 4));
                }
#pragma unroll
                for (int mt = 0; mt < 4; mt++) {
                    int rA = wm * 64 + mt * 16 + lrow;
                    ldsm4(a[mt], s0 + SWA(rA, ch));
                }
#pragma unroll
                for (int mt = 0; mt < 4; mt++)
#pragma unroll
                    for (int nn = 0; nn < 4; nn++) {
                        int q = nn >> 1, h = nn & 1;
                        mma16816(acc[mt][nn], a[mt], bH[q][h], bH[q][h + 2]);
                        mma16816(acc[mt][nn], a[mt], bL[q][h], bL[q][h + 2]);
                    }
#pragma unroll
                for (int mt = 0; mt < 4; mt++) {
                    int rA = wm * 64 + mt * 16 + lrow;
                    ldsm4(a[mt], s0 + SWA(rA, ch + 4));
                }
#pragma unroll
                for (int mt = 0; mt < 4; mt++)
#pragma unroll
                    for (int nn = 0; nn < 4; nn++) {
                        int q = nn >> 1, h = nn & 1;
                        mma16816(acc[mt][nn], a[mt], bH[q][h], bH[q][h + 2]);
                    }
            }
        };

        issue(0, 0);
        issue(1, STG_SZ);
        for (int mj = 0; mj < 7; mj++) {
            int b0 = mj * 3;
            CP_WAIT1(); __syncthreads(); issue(b0 + 2, 2 * STG_SZ); compute(smb);
            CP_WAIT1(); __syncthreads(); issue(b0 + 3, 0);          compute(smb + STG_SZ);
            CP_WAIT1(); __syncthreads(); issue(b0 + 4, STG_SZ);     compute(smb + 2 * STG_SZ);
        }
        CP_WAIT1(); __syncthreads(); issue(23, 2 * STG_SZ); compute(smb);
        CP_WAIT1(); __syncthreads();                         compute(smb + STG_SZ);
        CP_WAIT0(); __syncthreads();                         compute(smb + 2 * STG_SZ);

        // epilogue: gated = tanh(f)*sigmoid(g), write hi/lo splits
        const float* cbf = conv_b + layer * 512;
        const int lm = lid >> 2, ln = lid & 3;
#pragma unroll
        for (int mt = 0; mt < 4; mt++) {
            int row0 = m0 + wm * 64 + mt * 16 + lm;
#pragma unroll
            for (int nn = 0; nn < 4; nn++) {
                int ch = ((n0 + wn * 32 + nn * 8) >> 1) + ln;
                float fb = __ldg(cbf + ch), gb = __ldg(cbf + 256 + ch);
#pragma unroll
                for (int u = 0; u < 2; u++) {
                    int row = row0 + u * 8;
                    float f = acc[mt][nn][2 * u] + fb;
                    float g = acc[mt][nn][2 * u + 1] + gb;
                    float e2f = __expf(2.0f * f);
                    float th = (e2f - 1.0f) / (e2f + 1.0f);
                    float val = th / (1.0f + __expf(-g));
                    __nv_bfloat16 hi = __float2bfloat16(val);
                    g_ghi[(size_t)row * DH + ch] = hi;
                    g_glo[(size_t)row * DH + ch] = __float2bfloat16(val - __bfloat162float(hi));
                }
            }
        }
        __syncthreads();
        if (tid == 0) red_rel_add(&g_cdone[(layer * B_SZ + bidx) * 8 + ttile]);
    } else {
        const int s = rem - c_convn[layer];
        const int x = s & 1;
        const int y = s >> 1;
        const int per = nt + 1;
        const int bidx = y / per;
        const int j = y % per;
        const int ttile = (j < nt) ? (tstart + j) : 7;
        const int n0 = ((j < nt) ? 0 : 256) + x * 128;
        const int m0 = bidx * T_LEN + ttile * 128;

        // wait on conv of this layer for tiles [ttile .. min(ttile+2, 7)]
        if (tid == 0) {
            int hi_t = ttile + 2;
            if (hi_t > 7) hi_t = 7;
            for (int tp = ttile; tp <= hi_t; tp++) {
                int* f = &g_cdone[(layer * B_SZ + bidx) * 8 + tp];
                while (ld_acq(f) < 4) __nanosleep(64);
            }
        }
        __syncthreads();

        const __nv_bfloat16* Asrc = (lislo ? g_glo : g_ghi) + (size_t)m0 * DH + lc * 8;
        const __nv_bfloat16* Bsrc = (lislo ? g_Ws_lo : g_Ws_hi)
                                  + ((size_t)layer * 512 + n0) * DH + lc * 8;

        auto issue = [&](int it, uint32_t stgoff) {
            int kk = it * 32;
            uint32_t sb = smb + stgoff;
#pragma unroll
            for (int q = 0; q < 4; q++) {
                int r = q * 32 + lrr;
                uint32_t dst = sb + SWA(r, chunk);
                cp16(dst,        Asrc + (size_t)r * DH + kk, true);
                cp16(dst + SP_B, Bsrc + (size_t)r * DH + kk, true);
            }
            CP_COMMIT();
        };
        auto compute = [&](uint32_t s0) {
#pragma unroll
            for (int ks = 0; ks < 2; ks++) {
                int ch = 2 * ks + khalf;
                uint32_t a[4][4], bH[2][4], bL[2][4];
#pragma unroll
                for (int q = 0; q < 2; q++) {
                    int rB = wn * 32 + q * 16 + lrow;
                    ldsm4(bH[q], s0 + SP_B + SWA(rB, ch));
                    ldsm4(bL[q], s0 + SP_B + SWA(rB, ch + 4));
                }
#pragma unroll
                for (int mt = 0; mt < 4; mt++) {
                    int rA = wm * 64 + mt * 16 + lrow;
                    ldsm4(a[mt], s0 + SWA(rA, ch));
                }
#pragma unroll
                for (int mt = 0; mt < 4; mt++)
#pragma unroll
                    for (int nn = 0; nn < 4; nn++) {
                        int q = nn >> 1, h = nn & 1;
                        mma16816(acc[mt][nn], a[mt], bH[q][h], bH[q][h + 2]);
                        mma16816(acc[mt][nn], a[mt], bL[q][h], bL[q][h + 2]);
                    }
#pragma unroll
                for (int mt = 0; mt < 4; mt++) {
                    int rA = wm * 64 + mt * 16 + lrow;
                    ldsm4(a[mt], s0 + SWA(rA, ch + 4));
                }
#pragma unroll
                for (int mt = 0; mt < 4; mt++)
#pragma unroll
                    for (int nn = 0; nn < 4; nn++) {
                        int q = nn >> 1, h = nn & 1;
                        mma16816(acc[mt][nn], a[mt], bH[q][h], bH[q][h + 2]);
                    }
            }
        };

        issue(0, 0);
        issue(1, STG_SZ);
        CP_WAIT1(); __syncthreads(); issue(2, 2 * STG_SZ); compute(smb);
        CP_WAIT1(); __syncthreads(); issue(3, 0);          compute(smb + STG_SZ);
        CP_WAIT1(); __syncthreads(); issue(4, STG_SZ);     compute(smb + 2 * STG_SZ);
        CP_WAIT1(); __syncthreads(); issue(5, 2 * STG_SZ); compute(smb);
        CP_WAIT1(); __syncthreads(); issue(6, 0);          compute(smb + STG_SZ);
        CP_WAIT1(); __syncthreads(); issue(7, STG_SZ);     compute(smb + 2 * STG_SZ);
        CP_WAIT1(); __syncthreads();                       compute(smb);
        CP_WAIT0(); __syncthreads();                       compute(smb + STG_SZ);

        // epilogue
        const float* sb_ = skip_b + layer * 512;
        const int lm = lid >> 2, ln = lid & 3;
        const bool is_h = (n0 < 256);
#pragma unroll
        for (int mt = 0; mt < 4; mt++) {
            int row0 = m0 + wm * 64 + mt * 16 + lm;
#pragma unroll
            for (int nn = 0; nn < 4; nn++) {
                int oc = n0 + wn * 32 + nn * 8 + 2 * ln;
                float b0 = __ldg(sb_ + oc), b1 = __ldg(sb_ + oc + 1);
#pragma unroll
                for (int u = 0; u < 2; u++) {
                    int row = row0 + u * 8;
                    float v0 = acc[mt][nn][2 * u] + b0;
                    float v1 = acc[mt][nn][2 * u + 1] + b1;
                    if (is_h) {
                        float2* hp = (float2*)(g_h + (size_t)row * DH + oc);
                        float2 cur = *hp;
                        float nh0 = cur.x + v0, nh1 = cur.y + v1;
                        *hp = make_float2(nh0, nh1);
                        __nv_bfloat16 a0 = __float2bfloat16(nh0);
                        __nv_bfloat16 a1 = __float2bfloat16(nh1);
                        *(__nv_bfloat162*)(g_hhi + (size_t)row * DH + oc) = __nv_bfloat162(a0, a1);
                        *(__nv_bfloat162*)(g_hlo + (size_t)row * DH + oc) = __nv_bfloat162(
                            __float2bfloat16(nh0 - __bfloat162float(a0)),
                            __float2bfloat16(nh1 - __bfloat162float(a1)));
                    } else {
                        float2* sp = (float2*)(g_skip + (size_t)row * DH + (oc - 256));
                        float2 prev = (layer == 0) ? make_float2(0.f, 0.f) : *sp;
                        *sp = make_float2(prev.x + v0, prev.y + v1);
                    }
                }
            }
        }
        __syncthreads();
        if (tid == 0) red_rel_add(&g_sdone[(layer * B_SZ + bidx) * 8 + ttile]);
    }
}

// ---------------- FC head + Gaussian NLL ------------------------------------
__global__ __launch_bounds__(256) void final_k(
    const float* __restrict__ y,
    const float* __restrict__ fc_w, const float* __restrict__ fc_b,
    const float* __restrict__ loc_w, const float* __restrict__ loc_b,
    const float* __restrict__ scale_w, const float* __restrict__ scale_b,
    float* __restrict__ out) {
    int row = blockIdx.x;
    int tt = row >> 6;
    int b = row & 63;
    int t = T_LEN - OUTL + tt;
    size_t r = (size_t)b * T_LEN + t;
    __shared__ float srow[DH];
    __shared__ float red[256];
    int c = threadIdx.x;
    srow[c] = g_skip[r * DH + c];
    __syncthreads();
    float acc = fc_b[c];
#pragma unroll 8
    for (int k = 0; k < DH; k++) acc += srow[k] * fc_w[k * DH + c];
    float ff = fmaxf(acc, 0.0f);

    red[c] = ff * loc_w[c];
    __syncthreads();
    for (int s = 128; s > 0; s >>= 1) {
        if (c < s) red[c] += red[c + s];
        __syncthreads();
    }
    float loc = red[0] + loc_b[0];
    __syncthreads();

    red[c] = ff * scale_w[c];
    __syncthreads();
    for (int s = 128; s > 0; s >>= 1) {
        if (c < s) red[c] += red[c + s];
        __syncthreads();
    }
    if (c == 0) {
        float sraw = red[0] + scale_b[0];
        float sp = (sraw > 20.0f) ? sraw : log1pf(expf(sraw));
        float scale = sp + 1e-6f;
        float yt = y[(size_t)t * B_SZ + b];
        float z = (yt - loc) / scale;
        float lp = -0.5f * z * z - logf(scale) - 0.91893853320467274f;
        out[2 + row] = loc;
        out[2 + OUTL * B_SZ + row] = scale;
        atomicAdd(&g_loss, lp);
    }
}

__global__ void finish_k(float* __restrict__ out) {
    float L = -g_loss / (float)(OUTL * B_SZ);
    out[0] = L;
    out[1] = L;
}

// ---------------- launch -----------------------------------------------------
extern "C" void kernel_launch(void* const* d_in, const int* in_sizes, int n_in,
                              void* d_out, int out_size) {
    const float* X_cov   = (const float*)d_in[1];
    const float* X_lag   = (const float*)d_in[2];
    const float* y       = (const float*)d_in[3];
    const float* up_w    = (const float*)d_in[5];
    const float* up_b    = (const float*)d_in[6];
    const float* conv_w  = (const float*)d_in[7];
    const float* conv_b  = (const float*)d_in[8];
    const float* skip_w  = (const float*)d_in[9];
    const float* skip_b  = (const float*)d_in[10];
    const float* fc_w    = (const float*)d_in[11];
    const float* fc_b    = (const float*)d_in[12];
    const float* loc_w   = (const float*)d_in[13];
    const float* loc_b   = (const float*)d_in[14];
    const float* scale_w = (const float*)d_in[15];
    const float* scale_b = (const float*)d_in[16];
    float* out = (float*)d_out;

    cudaFuncSetAttribute(mega, cudaFuncAttributeMaxDynamicSharedMemorySize, SMEM_DYN);

    const int prepTot = NL * 3 * 512 * DH;
    prep_weights<<<(prepTot + 255) / 256, 256>>>(conv_w, skip_w);
    up_kernel<<<B_SZ * (T_LEN - UP_T0), 256>>>(X_lag, X_cov, up_w, up_b);
    mega<<<MEGA_BLOCKS, 256, SMEM_DYN>>>(conv_b, skip_b);
    final_k<<<OUTL * B_SZ, 256>>>(y, fc_w, fc_b, loc_w, loc_b, scale_w, scale_b, out);
    finish_k<<<1, 1>>>(out);
}

// round 10
// speedup vs baseline: 5.5977x; 1.0051x over previous
#include <cuda_runtime.h>
#include <cuda_bf16.h>
#include <cstdint>
#include <math.h>

#define T_LEN 1024
#define B_SZ  64
#define DH    256
#define NL    8
#define OUTL  24
#define M_TOT (B_SZ * T_LEN)
#define UP_T0 376                 // first timestep whose h is ever read

// ---------------- device scratch -------------------------------------------
__device__ __align__(128) float          g_h   [M_TOT * DH];
__device__ __align__(128) float          g_skip[M_TOT * DH];
__device__ __align__(128) __nv_bfloat16  g_hhi [M_TOT * DH];
__device__ __align__(128) __nv_bfloat16  g_hlo [M_TOT * DH];
__device__ __align__(128) __nv_bfloat16  g_ghi [M_TOT * DH];
__device__ __align__(128) __nv_bfloat16  g_glo [M_TOT * DH];
__device__ __align__(128) __nv_bfloat16  g_Wc_hi[NL * 3 * 512 * DH];
__device__ __align__(128) __nv_bfloat16  g_Wc_lo[NL * 3 * 512 * DH];
__device__ __align__(128) __nv_bfloat16  g_Ws_hi[NL * 512 * DH];
__device__ __align__(128) __nv_bfloat16  g_Ws_lo[NL * 512 * DH];
__device__ float g_loss;
// dependency flags: per (layer, batch, t-tile)
__device__ int g_cdone[NL * B_SZ * 8];
__device__ int g_sdone[NL * B_SZ * 8];

// layer schedule
__constant__ int c_ts[NL]    = {3, 3, 3, 4, 4, 4, 5, 7};
__constant__ int c_convn[NL] = {2560, 2560, 2560, 2048, 2048, 2048, 1536, 512}; // 512*nt
__constant__ int c_skipn[NL] = {1536, 1536, 1536, 1280, 1280, 1280, 1024, 512}; // 256*(nt+1)
#define MEGA_BLOCKS 25856

// ---------------- PTX helpers ------------------------------------------------
__device__ __forceinline__ uint32_t cvta_s(const void* p) {
    uint32_t a;
    asm("{ .reg .u64 t; cvta.to.shared.u64 t, %1; cvt.u32.u64 %0, t; }" : "=r"(a) : "l"(p));
    return a;
}
__device__ __forceinline__ void ldsm4(uint32_t (&r)[4], uint32_t addr) {
    asm volatile("ldmatrix.sync.aligned.m8n8.x4.shared.b16 {%0,%1,%2,%3}, [%4];"
                 : "=r"(r[0]), "=r"(r[1]), "=r"(r[2]), "=r"(r[3]) : "r"(addr));
}
__device__ __forceinline__ void mma16816(float (&c)[4], const uint32_t (&a)[4],
                                         uint32_t b0, uint32_t b1) {
    asm volatile(
        "mma.sync.aligned.m16n8k16.row.col.f32.bf16.bf16.f32 "
        "{%0,%1,%2,%3}, {%4,%5,%6,%7}, {%8,%9}, {%0,%1,%2,%3};"
        : "+f"(c[0]), "+f"(c[1]), "+f"(c[2]), "+f"(c[3])
        : "r"(a[0]), "r"(a[1]), "r"(a[2]), "r"(a[3]), "r"(b0), "r"(b1));
}
__device__ __forceinline__ void cp16(uint32_t saddr, const void* g, bool pred) {
    int sz = pred ? 16 : 0;
    asm volatile("cp.async.cg.shared.global [%0], [%1], 16, %2;"
                 :: "r"(saddr), "l"(g), "r"(sz) : "memory");
}
#define CP_COMMIT() asm volatile("cp.async.commit_group;" ::: "memory")
#define CP_WAIT1()  asm volatile("cp.async.wait_group 1;" ::: "memory")
#define CP_WAIT0()  asm volatile("cp.async.wait_group 0;" ::: "memory")

__device__ __forceinline__ int ld_acq(const int* p) {
    int v;
    asm volatile("ld.acquire.gpu.global.b32 %0, [%1];" : "=r"(v) : "l"(p) : "memory");
    return v;
}
__device__ __forceinline__ void red_rel_add(int* p) {
    asm volatile("red.release.gpu.global.add.s32 [%0], 1;" :: "l"(p) : "memory");
}

// Stage: superplane A @0 (128 rows x 128B = [hi|lo]), B @16KB (64 rows x 128B).
#define SP_B  16384
#define STG_SZ 24576
#define SMEM_DYN (3 * STG_SZ)
#define SWA(r, c) ((uint32_t)((r) * 128 + (((c) ^ ((r) & 7)) << 4)))

// ---------------- weight pack + flag zero -------------------------------------
__global__ void prep_weights(const float* __restrict__ conv_w,
                             const float* __restrict__ skip_w) {
    int idx = blockIdx.x * blockDim.x + threadIdx.x;
    if (idx == 0) g_loss = 0.0f;
    if (idx < NL * B_SZ * 8) { g_cdone[idx] = 0; g_sdone[idx] = 0; }
    const int totC = NL * 3 * 512 * DH;
    if (idx < totC) {
        int ic = idx & 255;
        int np = (idx >> 8) & 511;
        int tap = (idx >> 17) % 3;
        int layer = idx / (3 * 512 * 256);
        int c = np >> 1, s = np & 1;
        int oc = c + s * 256;
        float v = conv_w[((size_t)(layer * 512 + oc) * DH + ic) * 3 + tap];
        __nv_bfloat16 hi = __float2bfloat16(v);
        g_Wc_hi[idx] = hi;
        g_Wc_lo[idx] = __float2bfloat16(v - __bfloat162float(hi));
    }
    const int totS = NL * 512 * DH;
    if (idx < totS) {
        float v = skip_w[idx];
        __nv_bfloat16 hi = __float2bfloat16(v);
        g_Ws_hi[idx] = hi;
        g_Ws_lo[idx] = __float2bfloat16(v - __bfloat162float(hi));
    }
}

// ---------------- up projection ------------------------------------------------
__global__ __launch_bounds__(256) void up_kernel(
    const float* __restrict__ X_lag, const float* __restrict__ X_cov,
    const float* __restrict__ up_w, const float* __restrict__ up_b) {
    const int span = T_LEN - UP_T0;
    int blk = blockIdx.x;
    int b = blk / span;
    int t = UP_T0 + blk % span;
    int r = b * T_LEN + t;
    __shared__ float x[16];
    int c = threadIdx.x;
    if (c < 8)       x[c] = X_lag[((size_t)t * B_SZ + b) * 8 + c];
    else if (c < 16) x[c] = X_cov[((size_t)t * B_SZ + b) * 8 + (c - 8)];
    __syncthreads();
    float acc = up_b[c];
#pragma unroll
    for (int j = 0; j < 16; j++) acc += x[j] * up_w[j * DH + c];
    size_t o = (size_t)r * DH + c;
    g_h[o] = acc;
    __nv_bfloat16 hi = __float2bfloat16(acc);
    g_hhi[o] = hi;
    g_hlo[o] = __float2bfloat16(acc - __bfloat162float(hi));
}

// ---------------- mega kernel: CTA tile 128x64, 3 CTAs/SM ---------------------
__global__ __launch_bounds__(256, 3) void mega(const float* __restrict__ conv_b,
                                               const float* __restrict__ skip_b) {
    extern __shared__ __align__(16) unsigned char sm[];
    int rem = blockIdx.x;
    int layer = 0;
    while (layer < NL - 1 && rem >= c_convn[layer] + c_skipn[layer]) {
        rem -= c_convn[layer] + c_skipn[layer];
        layer++;
    }
    const int tstart = c_ts[layer];
    const int nt = 8 - tstart;
    const bool isconv = rem < c_convn[layer];

    const int tid = threadIdx.x, wid = tid >> 5, lid = tid & 31;
    const int wm = wid & 3, wn = wid >> 2;          // warp tile 32x32
    const uint32_t smb = cvta_s(sm);
    const int lrow = lid & 15, khalf = lid >> 4;
    const int lc = tid & 3, lislo = (tid >> 2) & 1, lrr = tid >> 3;
    const int chunk = lislo * 4 + lc;

    float acc[2][4][4];
#pragma unroll
    for (int a = 0; a < 2; a++)
#pragma unroll
        for (int b = 0; b < 4; b++)
#pragma unroll
            for (int d = 0; d < 4; d++) acc[a][b][d] = 0.0f;

    if (isconv) {
        const int nx = rem & 7;                     // 8 N-tiles of 64
        const int y = rem >> 3;
        const int bidx = y / nt;
        const int ttile = tstart + y % nt;
        const int n0 = nx * 64;
        const int m0 = bidx * T_LEN + ttile * 128;
        const int t0 = ttile * 128;
        const int dil = 1 << layer;

        if (layer > 0 && tid == 0) {
            int lo = ttile - 2, tsp = c_ts[layer - 1];
            if (lo < tsp) lo = tsp;
            for (int tp = lo; tp <= ttile; tp++) {
                int tgt = (tp == 7) ? 8 : 4;
                int* f = &g_sdone[((layer - 1) * B_SZ + bidx) * 8 + tp];
                while (ld_acq(f) < tgt) __nanosleep(64);
            }
        }
        __syncthreads();

        auto issue = [&](int it, uint32_t stgoff) {
            int tap = it >> 3, kc = it & 7;
            int kk = kc * 32;
            int off = (2 - tap) * dil;
            const __nv_bfloat16* Asrc = (lislo ? g_hlo : g_hhi)
                                      + ((long)(m0 - off) * DH + kk) + lc * 8;
            const __nv_bfloat16* Bsrc = (lislo ? g_Wc_lo : g_Wc_hi)
                                      + ((size_t)(layer * 3 + tap) * 512 + n0) * DH + kk + lc * 8;
            uint32_t sb = smb + stgoff;
#pragma unroll
            for (int q = 0; q < 4; q++) {
                int r = q * 32 + lrr;
                cp16(sb + SWA(r, chunk), Asrc + (size_t)r * DH, (t0 + r) >= off);
            }
#pragma unroll
            for (int q = 0; q < 2; q++) {
                int r = q * 32 + lrr;
                cp16(sb + SP_B + SWA(r, chunk), Bsrc + (size_t)r * DH, true);
            }
            CP_COMMIT();
        };
        auto compute = [&](uint32_t s0) {
#pragma unroll
            for (int ks = 0; ks < 2; ks++) {
                int ch = 2 * ks + khalf;
                uint32_t a[2][4], bH[2][4], bL[2][4];
#pragma unroll
                for (int q = 0; q < 2; q++) {
                    int rB = wn * 32 + q * 16 + lrow;
                    ldsm4(bH[q], s0 + SP_B + SWA(rB, ch));
                    ldsm4(bL[q], s0 + SP_B + SWA(rB, ch + 4));
                }
#pragma unroll
                for (int mt = 0; mt < 2; mt++)
                    ldsm4(a[mt], s0 + SWA(wm * 32 + mt * 16 + lrow, ch));
#pragma unroll
                for (int mt = 0; mt < 2; mt++)
#pragma unroll
                    for (int nn = 0; nn < 4; nn++) {
                        int q = nn >> 1, h = nn & 1;
                        mma16816(acc[mt][nn], a[mt], bH[q][h], bH[q][h + 2]);
                        mma16816(acc[mt][nn], a[mt], bL[q][h], bL[q][h + 2]);
                    }
#pragma unroll
                for (int mt = 0; mt < 2; mt++)
                    ldsm4(a[mt], s0 + SWA(wm * 32 + mt * 16 + lrow, ch + 4));
#pragma unroll
                for (int mt = 0; mt < 2; mt++)
#pragma unroll
                    for (int nn = 0; nn < 4; nn++) {
                        int q = nn >> 1, h = nn & 1;
                        mma16816(acc[mt][nn], a[mt], bH[q][h], bH[q][h + 2]);
                    }
            }
        };

        issue(0, 0);
        issue(1, STG_SZ);
        for (int mj = 0; mj < 7; mj++) {
            int b0 = mj * 3;
            CP_WAIT1(); __syncthreads(); issue(b0 + 2, 2 * STG_SZ); compute(smb);
            CP_WAIT1(); __syncthreads(); issue(b0 + 3, 0);          compute(smb + STG_SZ);
            CP_WAIT1(); __syncthreads(); issue(b0 + 4, STG_SZ);     compute(smb + 2 * STG_SZ);
        }
        CP_WAIT1(); __syncthreads(); issue(23, 2 * STG_SZ); compute(smb);
        CP_WAIT1(); __syncthreads();                         compute(smb + STG_SZ);
        CP_WAIT0(); __syncthreads();                         compute(smb + 2 * STG_SZ);

        // epilogue: gated = tanh(f)*sigmoid(g)
        const float* cbf = conv_b + layer * 512;
        const int lm = lid >> 2, ln = lid & 3;
#pragma unroll
        for (int mt = 0; mt < 2; mt++) {
            int row0 = m0 + wm * 32 + mt * 16 + lm;
#pragma unroll
            for (int nn = 0; nn < 4; nn++) {
                int ch = ((n0 + wn * 32 + nn * 8) >> 1) + ln;
                float fb = __ldg(cbf + ch), gb = __ldg(cbf + 256 + ch);
#pragma unroll
                for (int u = 0; u < 2; u++) {
                    int row = row0 + u * 8;
                    float f = acc[mt][nn][2 * u] + fb;
                    float g = acc[mt][nn][2 * u + 1] + gb;
                    float e2f = __expf(2.0f * f);
                    float th = (e2f - 1.0f) / (e2f + 1.0f);
                    float val = th / (1.0f + __expf(-g));
                    __nv_bfloat16 hi = __float2bfloat16(val);
                    g_ghi[(size_t)row * DH + ch] = hi;
                    g_glo[(size_t)row * DH + ch] = __float2bfloat16(val - __bfloat162float(hi));
                }
            }
        }
        __syncthreads();
        if (tid == 0) red_rel_add(&g_cdone[(layer * B_SZ + bidx) * 8 + ttile]);
    } else {
        const int s = rem - c_convn[layer];
        const int x = s & 3;                        // 4 N-tiles of 64 per half
        const int y = s >> 2;
        const int per = nt + 1;
        const int bidx = y / per;
        const int j = y % per;
        const int ttile = (j < nt) ? (tstart + j) : 7;
        const int n0 = ((j < nt) ? 0 : 256) + x * 64;
        const int m0 = bidx * T_LEN + ttile * 128;

        if (tid == 0) {
            int hi_t = ttile + 2;
            if (hi_t > 7) hi_t = 7;
            for (int tp = ttile; tp <= hi_t; tp++) {
                int* f = &g_cdone[(layer * B_SZ + bidx) * 8 + tp];
                while (ld_acq(f) < 8) __nanosleep(64);
            }
        }
        __syncthreads();

        const __nv_bfloat16* Asrc = (lislo ? g_glo : g_ghi) + (size_t)m0 * DH + lc * 8;
        const __nv_bfloat16* Bsrc = (lislo ? g_Ws_lo : g_Ws_hi)
                                  + ((size_t)layer * 512 + n0) * DH + lc * 8;

        auto issue = [&](int it, uint32_t stgoff) {
            int kk = it * 32;
            uint32_t sb = smb + stgoff;
#pragma unroll
            for (int q = 0; q < 4; q++) {
                int r = q * 32 + lrr;
                cp16(sb + SWA(r, chunk), Asrc + (size_t)r * DH + kk, true);
            }
#pragma unroll
            for (int q = 0; q < 2; q++) {
                int r = q * 32 + lrr;
                cp16(sb + SP_B + SWA(r, chunk), Bsrc + (size_t)r * DH + kk, true);
            }
            CP_COMMIT();
        };
        auto compute = [&](uint32_t s0) {
#pragma unroll
            for (int ks = 0; ks < 2; ks++) {
                int ch = 2 * ks + khalf;
                uint32_t a[2][4], bH[2][4], bL[2][4];
#pragma unroll
                for (int q = 0; q < 2; q++) {
                    int rB = wn * 32 + q * 16 + lrow;
                    ldsm4(bH[q], s0 + SP_B + SWA(rB, ch));
                    ldsm4(bL[q], s0 + SP_B + SWA(rB, ch + 4));
                }
#pragma unroll
                for (int mt = 0; mt < 2; mt++)
                    ldsm4(a[mt], s0 + SWA(wm * 32 + mt * 16 + lrow, ch));
#pragma unroll
                for (int mt = 0; mt < 2; mt++)
#pragma unroll
                    for (int nn = 0; nn < 4; nn++) {
                        int q = nn >> 1, h = nn & 1;
                        mma16816(acc[mt][nn], a[mt], bH[q][h], bH[q][h + 2]);
                        mma16816(acc[mt][nn], a[mt], bL[q][h], bL[q][h + 2]);
                    }
#pragma unroll
                for (int mt = 0; mt < 2; mt++)
                    ldsm4(a[mt], s0 + SWA(wm * 32 + mt * 16 + lrow, ch + 4));
#pragma unroll
                for (int mt = 0; mt < 2; mt++)
#pragma unroll
                    for (int nn = 0; nn < 4; nn++) {
                        int q = nn >> 1, h = nn & 1;
                        mma16816(acc[mt][nn], a[mt], bH[q][h], bH[q][h + 2]);
                    }
            }
        };

        issue(0, 0);
        issue(1, STG_SZ);
        CP_WAIT1(); __syncthreads(); issue(2, 2 * STG_SZ); compute(smb);
        CP_WAIT1(); __syncthreads(); issue(3, 0);          compute(smb + STG_SZ);
        CP_WAIT1(); __syncthreads(); issue(4, STG_SZ);     compute(smb + 2 * STG_SZ);
        CP_WAIT1(); __syncthreads(); issue(5, 2 * STG_SZ); compute(smb);
        CP_WAIT1(); __syncthreads(); issue(6, 0);          compute(smb + STG_SZ);
        CP_WAIT1(); __syncthreads(); issue(7, STG_SZ);     compute(smb + 2 * STG_SZ);
        CP_WAIT1(); __syncthreads();                       compute(smb);
        CP_WAIT0(); __syncthreads();                       compute(smb + STG_SZ);

        // epilogue
        const float* sb_ = skip_b + layer * 512;
        const int lm = lid >> 2, ln = lid & 3;
        const bool is_h = (n0 < 256);
#pragma unroll
        for (int mt = 0; mt < 2; mt++) {
            int row0 = m0 + wm * 32 + mt * 16 + lm;
#pragma unroll
            for (int nn = 0; nn < 4; nn++) {
                int oc = n0 + wn * 32 + nn * 8 + 2 * ln;
                float b0 = __ldg(sb_ + oc), b1 = __ldg(sb_ + oc + 1);
#pragma unroll
                for (int u = 0; u < 2; u++) {
                    int row = row0 + u * 8;
                    float v0 = acc[mt][nn][2 * u] + b0;
                    float v1 = acc[mt][nn][2 * u + 1] + b1;
                    if (is_h) {
                        float2* hp = (float2*)(g_h + (size_t)row * DH + oc);
                        float2 cur = *hp;
                        float nh0 = cur.x + v0, nh1 = cur.y + v1;
                        *hp = make_float2(nh0, nh1);
                        __nv_bfloat16 a0 = __float2bfloat16(nh0);
                        __nv_bfloat16 a1 = __float2bfloat16(nh1);
                        *(__nv_bfloat162*)(g_hhi + (size_t)row * DH + oc) = __nv_bfloat162(a0, a1);
                        *(__nv_bfloat162*)(g_hlo + (size_t)row * DH + oc) = __nv_bfloat162(
                            __float2bfloat16(nh0 - __bfloat162float(a0)),
                            __float2bfloat16(nh1 - __bfloat162float(a1)));
                    } else {
                        float2* sp = (float2*)(g_skip + (size_t)row * DH + (oc - 256));
                        float2 prev = (layer == 0) ? make_float2(0.f, 0.f) : *sp;
                        *sp = make_float2(prev.x + v0, prev.y + v1);
                    }
                }
            }
        }
        __syncthreads();
        if (tid == 0) red_rel_add(&g_sdone[(layer * B_SZ + bidx) * 8 + ttile]);
    }
}

// ---------------- FC head + Gaussian NLL (4 rows per block) -------------------
__global__ __launch_bounds__(256) void final_k(
    const float* __restrict__ y,
    const float* __restrict__ fc_w, const float* __restrict__ fc_b,
    const float* __restrict__ loc_w, const float* __restrict__ loc_b,
    const float* __restrict__ scale_w, const float* __restrict__ scale_b,
    float* __restrict__ out) {
    __shared__ float srow[4][DH];
    __shared__ float red[256];
    int c = threadIdx.x;
#pragma unroll
    for (int rr = 0; rr < 4; rr++) {
        int row = blockIdx.x * 4 + rr;
        int tt = row >> 6, b = row & 63;
        int t = T_LEN - OUTL + tt;
        srow[rr][c] = g_skip[((size_t)b * T_LEN + t) * DH + c];
    }
    __syncthreads();
    float acc4[4];
#pragma unroll
    for (int rr = 0; rr < 4; rr++) acc4[rr] = fc_b[c];
#pragma unroll 4
    for (int k = 0; k < DH; k++) {
        float w = fc_w[k * DH + c];
#pragma unroll
        for (int rr = 0; rr < 4; rr++) acc4[rr] += srow[rr][k] * w;
    }
    float lw = loc_w[c], sw = scale_w[c];
#pragma unroll
    for (int rr = 0; rr < 4; rr++) {
        float ff = fmaxf(acc4[rr], 0.0f);
        red[c] = ff * lw;
        __syncthreads();
        for (int s = 128; s > 0; s >>= 1) {
            if (c < s) red[c] += red[c + s];
            __syncthreads();
        }
        float loc = red[0] + loc_b[0];
        __syncthreads();
        red[c] = ff * sw;
        __syncthreads();
        for (int s = 128; s > 0; s >>= 1) {
            if (c < s) red[c] += red[c + s];
            __syncthreads();
        }
        if (c == 0) {
            int row = blockIdx.x * 4 + rr;
            int tt = row >> 6, b = row & 63;
            int t = T_LEN - OUTL + tt;
            float sraw = red[0] + scale_b[0];
            float sp = (sraw > 20.0f) ? sraw : log1pf(expf(sraw));
            float scale = sp + 1e-6f;
            float yt = y[(size_t)t * B_SZ + b];
            float z = (yt - loc) / scale;
            float lp = -0.5f * z * z - logf(scale) - 0.91893853320467274f;
            out[2 + row] = loc;
            out[2 + OUTL * B_SZ + row] = scale;
            atomicAdd(&g_loss, lp);
        }
        __syncthreads();
    }
}

__global__ void finish_k(float* __restrict__ out) {
    float L = -g_loss / (float)(OUTL * B_SZ);
    out[0] = L;
    out[1] = L;
}

// ---------------- launch -----------------------------------------------------
extern "C" void kernel_launch(void* const* d_in, const int* in_sizes, int n_in,
                              void* d_out, int out_size) {
    const float* X_cov   = (const float*)d_in[1];
    const float* X_lag   = (const float*)d_in[2];
    const float* y       = (const float*)d_in[3];
    const float* up_w    = (const float*)d_in[5];
    const float* up_b    = (const float*)d_in[6];
    const float* conv_w  = (const float*)d_in[7];
    const float* conv_b  = (const float*)d_in[8];
    const float* skip_w  = (const float*)d_in[9];
    const float* skip_b  = (const float*)d_in[10];
    const float* fc_w    = (const float*)d_in[11];
    const float* fc_b    = (const float*)d_in[12];
    const float* loc_w   = (const float*)d_in[13];
    const float* loc_b   = (const float*)d_in[14];
    const float* scale_w = (const float*)d_in[15];
    const float* scale_b = (const float*)d_in[16];
    float* out = (float*)d_out;

    cudaFuncSetAttribute(mega, cudaFuncAttributeMaxDynamicSharedMemorySize, SMEM_DYN);

    const int prepTot = NL * 3 * 512 * DH;
    prep_weights<<<(prepTot + 255) / 256, 256>>>(conv_w, skip_w);
    up_kernel<<<B_SZ * (T_LEN - UP_T0), 256>>>(X_lag, X_cov, up_w, up_b);
    mega<<<MEGA_BLOCKS, 256, SMEM_DYN>>>(conv_b, skip_b);
    final_k<<<OUTL * B_SZ / 4, 256>>>(y, fc_w, fc_b, loc_w, loc_b, scale_w, scale_b, out);
    finish_k<<<1, 1>>>(out);
}